// round 1
// baseline (speedup 1.0000x reference)
#include <cuda_runtime.h>
#include <cuda_bf16.h>
#include <cstddef>

// Problem constants
#define B_  4
#define S_  1024
#define E_  1024
#define H_  16
#define HD_ 64
#define ML_ 2048
#define M_ROWS (B_ * S_)   // 4096

// ---------------- scratch (static device arrays; no allocation allowed) ----------------
__device__ float g_xn [M_ROWS * E_];        // LN1 output
__device__ float g_qkv[M_ROWS * 3 * E_];    // QKV projection output [token][3E]
__device__ float g_ao [M_ROWS * E_];        // attention output in [b,s,e] layout
__device__ float g_x1 [M_ROWS * E_];        // x + attn proj (residual 1)
__device__ float g_xm [M_ROWS * E_];        // LN2 output
__device__ float g_h1 [M_ROWS * 4 * E_];    // MLP hidden

// ---------------- LayerNorm: one block per row of 1024 ----------------
__global__ __launch_bounds__(256) void ln_kernel(const float* __restrict__ x,
                                                 const float* __restrict__ gamma,
                                                 const float* __restrict__ beta,
                                                 float* __restrict__ y)
{
    const int row = blockIdx.x;
    const int t   = threadIdx.x;
    const float* xr = x + (size_t)row * E_;

    float4 xv = *(const float4*)(xr + t * 4);
    float s  = xv.x + xv.y + xv.z + xv.w;
    float sq = xv.x * xv.x + xv.y * xv.y + xv.z * xv.z + xv.w * xv.w;

    // warp reduce
    #pragma unroll
    for (int o = 16; o > 0; o >>= 1) {
        s  += __shfl_down_sync(0xffffffffu, s,  o);
        sq += __shfl_down_sync(0xffffffffu, sq, o);
    }
    __shared__ float sa[8], sb[8];
    const int w = t >> 5, lane = t & 31;
    if (lane == 0) { sa[w] = s; sb[w] = sq; }
    __syncthreads();
    float ts = 0.f, tq = 0.f;
    #pragma unroll
    for (int k = 0; k < 8; k++) { ts += sa[k]; tq += sb[k]; }

    const float mean = ts * (1.0f / E_);
    const float var  = tq * (1.0f / E_) - mean * mean;
    const float rstd = rsqrtf(var + 1e-5f);

    float4 gv = *(const float4*)(gamma + t * 4);
    float4 bv = *(const float4*)(beta  + t * 4);
    float4 out;
    out.x = (xv.x - mean) * rstd * gv.x + bv.x;
    out.y = (xv.y - mean) * rstd * gv.y + bv.y;
    out.z = (xv.z - mean) * rstd * gv.z + bv.z;
    out.w = (xv.w - mean) * rstd * gv.w + bv.w;
    *(float4*)(y + (size_t)row * E_ + t * 4) = out;
}

// ---------------- NT SGEMM: C[M,N] = A[M,K] (row-major) * B[N,K]^T (row-major) + bias ----------------
// 128x128x8 tiles, 256 threads, 8x8 per-thread microtile, double-buffered SMEM.
#define BM 128
#define BN 128
#define BK 8

template <bool RELU, bool RES>
__global__ __launch_bounds__(256) void gemm_nt(const float* __restrict__ A,
                                               const float* __restrict__ Bm,
                                               const float* __restrict__ bias,
                                               const float* __restrict__ res,
                                               float* __restrict__ C,
                                               int M, int N, int K)
{
    __shared__ float As[2][BK][BM];
    __shared__ float Bs[2][BK][BN];

    const int tid = threadIdx.x;
    const int bm = blockIdx.y * BM;
    const int bn = blockIdx.x * BN;

    const int lr = tid >> 1;          // 0..127 : row within tile
    const int lk = (tid & 1) * 4;     // 0 or 4 : k offset
    const float* Ap = A  + (size_t)(bm + lr) * K + lk;
    const float* Bp = Bm + (size_t)(bn + lr) * K + lk;

    float acc[8][8];
    #pragma unroll
    for (int i = 0; i < 8; i++)
        #pragma unroll
        for (int j = 0; j < 8; j++) acc[i][j] = 0.f;

    // preload tile 0
    float4 a4 = *(const float4*)Ap;
    float4 b4 = *(const float4*)Bp;
    As[0][lk + 0][lr] = a4.x; As[0][lk + 1][lr] = a4.y;
    As[0][lk + 2][lr] = a4.z; As[0][lk + 3][lr] = a4.w;
    Bs[0][lk + 0][lr] = b4.x; Bs[0][lk + 1][lr] = b4.y;
    Bs[0][lk + 2][lr] = b4.z; Bs[0][lk + 3][lr] = b4.w;
    __syncthreads();

    const int tx = tid & 15;   // column group
    const int ty = tid >> 4;   // row group
    const int nk = K / BK;

    for (int kt = 0; kt < nk; kt++) {
        const int buf = kt & 1;
        if (kt + 1 < nk) {
            a4 = *(const float4*)(Ap + (size_t)(kt + 1) * BK);
            b4 = *(const float4*)(Bp + (size_t)(kt + 1) * BK);
        }
        #pragma unroll
        for (int kk = 0; kk < BK; kk++) {
            float a[8], b[8];
            *(float4*)&a[0] = *(const float4*)&As[buf][kk][ty * 8];
            *(float4*)&a[4] = *(const float4*)&As[buf][kk][ty * 8 + 4];
            *(float4*)&b[0] = *(const float4*)&Bs[buf][kk][tx * 8];
            *(float4*)&b[4] = *(const float4*)&Bs[buf][kk][tx * 8 + 4];
            #pragma unroll
            for (int i = 0; i < 8; i++)
                #pragma unroll
                for (int j = 0; j < 8; j++)
                    acc[i][j] += a[i] * b[j];
        }
        if (kt + 1 < nk) {
            const int nb = buf ^ 1;
            As[nb][lk + 0][lr] = a4.x; As[nb][lk + 1][lr] = a4.y;
            As[nb][lk + 2][lr] = a4.z; As[nb][lk + 3][lr] = a4.w;
            Bs[nb][lk + 0][lr] = b4.x; Bs[nb][lk + 1][lr] = b4.y;
            Bs[nb][lk + 2][lr] = b4.z; Bs[nb][lk + 3][lr] = b4.w;
            __syncthreads();
        }
    }

    // epilogue
    float bv[8];
    *(float4*)&bv[0] = *(const float4*)(bias + bn + tx * 8);
    *(float4*)&bv[4] = *(const float4*)(bias + bn + tx * 8 + 4);

    #pragma unroll
    for (int i = 0; i < 8; i++) {
        const size_t roff = (size_t)(bm + ty * 8 + i) * N + bn + tx * 8;
        float v[8];
        #pragma unroll
        for (int j = 0; j < 8; j++) {
            float t = acc[i][j] + bv[j];
            if (RELU) t = fmaxf(t, 0.f);
            v[j] = t;
        }
        if (RES) {
            float4 r0 = *(const float4*)(res + roff);
            float4 r1 = *(const float4*)(res + roff + 4);
            v[0] += r0.x; v[1] += r0.y; v[2] += r0.z; v[3] += r0.w;
            v[4] += r1.x; v[5] += r1.y; v[6] += r1.z; v[7] += r1.w;
        }
        *(float4*)(C + roff)     = *(float4*)&v[0];
        *(float4*)(C + roff + 4) = *(float4*)&v[4];
    }
}

// ---------------- Flash attention (causal + rel_pos bias), fp32 ----------------
// One thread per query row, 128 q rows per block. D=64 in registers.
#define BQ 128
#define TK 32

__global__ __launch_bounds__(128) void attn_kernel(const float* __restrict__ qkv,
                                                   const float* __restrict__ rel_pos,
                                                   float* __restrict__ out)
{
    __shared__ float Ks[TK][HD_];
    __shared__ float Vs[TK][HD_];

    const int t  = threadIdx.x;
    const int q0 = blockIdx.x * BQ;
    const int h  = blockIdx.y;
    const int b  = blockIdx.z;
    const int i  = q0 + t;            // this thread's query position

    const float* qrow = qkv + ((size_t)(b * S_ + i)) * (3 * E_) + h * HD_;
    float q[HD_];
    #pragma unroll
    for (int d = 0; d < HD_; d += 4) {
        float4 v = *(const float4*)(qrow + d);
        q[d]   = v.x * 0.125f;  // 1/sqrt(64)
        q[d+1] = v.y * 0.125f;
        q[d+2] = v.z * 0.125f;
        q[d+3] = v.w * 0.125f;
    }

    float o[HD_];
    #pragma unroll
    for (int d = 0; d < HD_; d++) o[d] = 0.f;
    float m = -1e30f, l = 0.f;

    const float* rp = rel_pos + (size_t)h * ML_;
    const int kend = q0 + BQ;

    for (int k0 = 0; k0 < kend; k0 += TK) {
        // cooperative load of K and V tiles [TK x 64]
        const float* kbase = qkv + ((size_t)(b * S_ + k0)) * (3 * E_) + E_     + h * HD_;
        const float* vbase = qkv + ((size_t)(b * S_ + k0)) * (3 * E_) + 2 * E_ + h * HD_;
        #pragma unroll
        for (int it = 0; it < (TK * (HD_ / 4)) / 128; it++) {
            const int idx = t + it * 128;
            const int row = idx >> 4;        // /16 float4s per row
            const int c4  = idx & 15;
            *(float4*)&Ks[row][c4 * 4] = *(const float4*)(kbase + (size_t)row * (3 * E_) + c4 * 4);
            *(float4*)&Vs[row][c4 * 4] = *(const float4*)(vbase + (size_t)row * (3 * E_) + c4 * 4);
        }
        __syncthreads();

        float sc[TK];
        float tmax = -1e30f;
        for (int j = 0; j < TK; j++) {
            const int kj = k0 + j;
            float s;
            if (kj <= i) {
                float acc = 0.f;
                #pragma unroll
                for (int d4 = 0; d4 < HD_ / 4; d4++) {
                    float4 kv = *(const float4*)&Ks[j][d4 * 4];
                    acc += q[d4*4]   * kv.x;
                    acc += q[d4*4+1] * kv.y;
                    acc += q[d4*4+2] * kv.z;
                    acc += q[d4*4+3] * kv.w;
                }
                s = acc + rp[i - kj];
            } else {
                s = -1e30f;
            }
            sc[j] = s;
            tmax = fmaxf(tmax, s);
        }

        const float mnew = fmaxf(m, tmax);
        const float corr = __expf(m - mnew);
        l *= corr;
        #pragma unroll
        for (int d = 0; d < HD_; d++) o[d] *= corr;

        for (int j = 0; j < TK; j++) {
            const float p = __expf(sc[j] - mnew);
            l += p;
            #pragma unroll
            for (int d4 = 0; d4 < HD_ / 4; d4++) {
                float4 vv = *(const float4*)&Vs[j][d4 * 4];
                o[d4*4]   += p * vv.x;
                o[d4*4+1] += p * vv.y;
                o[d4*4+2] += p * vv.z;
                o[d4*4+3] += p * vv.w;
            }
        }
        m = mnew;
        __syncthreads();
    }

    const float inv = 1.0f / l;
    float* op = out + ((size_t)(b * S_ + i)) * E_ + h * HD_;
    #pragma unroll
    for (int d4 = 0; d4 < HD_ / 4; d4++) {
        float4 v;
        v.x = o[d4*4]   * inv;
        v.y = o[d4*4+1] * inv;
        v.z = o[d4*4+2] * inv;
        v.w = o[d4*4+3] * inv;
        *(float4*)(op + d4 * 4) = v;
    }
}

// ---------------- launch ----------------
extern "C" void kernel_launch(void* const* d_in, const int* in_sizes, int n_in,
                              void* d_out, int out_size)
{
    const float* x         = (const float*)d_in[0];
    const float* rel_pos   = (const float*)d_in[1];
    const float* in_proj_w = (const float*)d_in[2];
    const float* in_proj_b = (const float*)d_in[3];
    const float* out_w     = (const float*)d_in[4];
    const float* out_b     = (const float*)d_in[5];
    const float* w1        = (const float*)d_in[6];
    const float* b1        = (const float*)d_in[7];
    const float* w2        = (const float*)d_in[8];
    const float* b2        = (const float*)d_in[9];
    const float* ln1_g     = (const float*)d_in[10];
    const float* ln1_b     = (const float*)d_in[11];
    const float* ln2_g     = (const float*)d_in[12];
    const float* ln2_b     = (const float*)d_in[13];
    float* out = (float*)d_out;

    float *p_xn, *p_qkv, *p_ao, *p_x1, *p_xm, *p_h1;
    cudaGetSymbolAddress((void**)&p_xn,  g_xn);
    cudaGetSymbolAddress((void**)&p_qkv, g_qkv);
    cudaGetSymbolAddress((void**)&p_ao,  g_ao);
    cudaGetSymbolAddress((void**)&p_x1,  g_x1);
    cudaGetSymbolAddress((void**)&p_xm,  g_xm);
    cudaGetSymbolAddress((void**)&p_h1,  g_h1);

    // 1) LN1
    ln_kernel<<<M_ROWS, 256>>>(x, ln1_g, ln1_b, p_xn);

    // 2) QKV projection: [4096,3072] = xn[4096,1024] @ in_proj_w[3072,1024]^T
    gemm_nt<false, false><<<dim3(3 * E_ / BN, M_ROWS / BM), 256>>>(
        p_xn, in_proj_w, in_proj_b, nullptr, p_qkv, M_ROWS, 3 * E_, E_);

    // 3) Attention
    attn_kernel<<<dim3(S_ / BQ, H_, B_), 128>>>(p_qkv, rel_pos, p_ao);

    // 4) Out projection + residual: x1 = x + ao @ out_w^T + out_b
    gemm_nt<false, true><<<dim3(E_ / BN, M_ROWS / BM), 256>>>(
        p_ao, out_w, out_b, x, p_x1, M_ROWS, E_, E_);

    // 5) LN2
    ln_kernel<<<M_ROWS, 256>>>(p_x1, ln2_g, ln2_b, p_xm);

    // 6) MLP up + ReLU: h1 = relu(xm @ w1^T + b1)   [4096,4096]
    gemm_nt<true, false><<<dim3(4 * E_ / BN, M_ROWS / BM), 256>>>(
        p_xm, w1, b1, nullptr, p_h1, M_ROWS, 4 * E_, E_);

    // 7) MLP down + residual: out = x1 + h1 @ w2^T + b2
    gemm_nt<false, true><<<dim3(E_ / BN, M_ROWS / BM), 256>>>(
        p_h1, w2, b2, p_x1, out, M_ROWS, E_, 4 * E_);
}

// round 3
// speedup vs baseline: 1.9220x; 1.9220x over previous
#include <cuda_runtime.h>
#include <cuda_bf16.h>
#include <cstdint>
#include <cstddef>

// Problem constants
#define B_  4
#define S_  1024
#define E_  1024
#define H_  16
#define HD_ 64
#define ML_ 2048
#define MR  4096   // B*S

typedef __nv_bfloat16 bf16;

// ---------------- static scratch ----------------
__device__ bf16  g_wqh[3*E_*E_], g_wql[3*E_*E_];
__device__ bf16  g_woh[E_*E_],   g_wol[E_*E_];
__device__ bf16  g_w1h[4*E_*E_], g_w1l[4*E_*E_];
__device__ bf16  g_w2h[4*E_*E_], g_w2l[4*E_*E_];
__device__ bf16  g_xnh[MR*E_],   g_xnl[MR*E_];
__device__ float g_qkv[(size_t)MR*3*E_];
__device__ bf16  g_aoh[MR*E_],   g_aol[MR*E_];
__device__ float g_x1 [MR*E_];
__device__ bf16  g_xmh[MR*E_],   g_xml[MR*E_];
__device__ bf16  g_h1h[(size_t)MR*4*E_], g_h1l[(size_t)MR*4*E_];

// ---------------- helpers ----------------
__device__ __forceinline__ uint32_t smem_u32(const void* p) {
    uint32_t a;
    asm("{ .reg .u64 t; cvta.to.shared.u64 t, %1; cvt.u32.u64 %0, t; }" : "=r"(a) : "l"(p));
    return a;
}
__device__ __forceinline__ void ldsm_x4(uint32_t* r, uint32_t addr) {
    asm volatile("ldmatrix.sync.aligned.m8n8.x4.shared.b16 {%0,%1,%2,%3}, [%4];"
        : "=r"(r[0]), "=r"(r[1]), "=r"(r[2]), "=r"(r[3]) : "r"(addr));
}
__device__ __forceinline__ void mma_bf16(float* d, const uint32_t* a, uint32_t b0, uint32_t b1) {
    asm volatile("mma.sync.aligned.m16n8k16.row.col.f32.bf16.bf16.f32 "
        "{%0,%1,%2,%3},{%4,%5,%6,%7},{%8,%9},{%0,%1,%2,%3};"
        : "+f"(d[0]), "+f"(d[1]), "+f"(d[2]), "+f"(d[3])
        : "r"(a[0]), "r"(a[1]), "r"(a[2]), "r"(a[3]), "r"(b0), "r"(b1));
}

// ---------------- weight/act split conversion ----------------
__global__ __launch_bounds__(256) void cvt_bf(const float* __restrict__ in,
                                              bf16* __restrict__ hi, bf16* __restrict__ lo, int n4)
{
    int i = blockIdx.x * blockDim.x + threadIdx.x;
    if (i >= n4) return;
    float4 v = ((const float4*)in)[i];
    union { bf16 b[4]; uint2 u; } ph, pl;
    float vv[4] = { v.x, v.y, v.z, v.w };
    #pragma unroll
    for (int k = 0; k < 4; k++) {
        bf16 h = __float2bfloat16(vv[k]);
        ph.b[k] = h;
        pl.b[k] = __float2bfloat16(vv[k] - __bfloat162float(h));
    }
    ((uint2*)hi)[i] = ph.u;
    ((uint2*)lo)[i] = pl.u;
}

// ---------------- LayerNorm -> bf16 hi/lo ----------------
__global__ __launch_bounds__(256) void ln_bf(const float* __restrict__ x,
                                             const float* __restrict__ gamma,
                                             const float* __restrict__ beta,
                                             bf16* __restrict__ yh, bf16* __restrict__ yl)
{
    const int row = blockIdx.x;
    const int t = threadIdx.x;
    const float* xr = x + (size_t)row * E_;
    float4 xv = *(const float4*)(xr + t * 4);
    float s = xv.x + xv.y + xv.z + xv.w;
    float sq = xv.x*xv.x + xv.y*xv.y + xv.z*xv.z + xv.w*xv.w;
    #pragma unroll
    for (int o = 16; o > 0; o >>= 1) {
        s  += __shfl_down_sync(0xffffffffu, s, o);
        sq += __shfl_down_sync(0xffffffffu, sq, o);
    }
    __shared__ float sa[8], sb[8];
    const int w = t >> 5, lane = t & 31;
    if (lane == 0) { sa[w] = s; sb[w] = sq; }
    __syncthreads();
    float ts = 0.f, tq = 0.f;
    #pragma unroll
    for (int k = 0; k < 8; k++) { ts += sa[k]; tq += sb[k]; }
    const float mean = ts * (1.0f / E_);
    const float var = tq * (1.0f / E_) - mean * mean;
    const float rstd = rsqrtf(var + 1e-5f);
    float4 gv = *(const float4*)(gamma + t * 4);
    float4 bv = *(const float4*)(beta + t * 4);
    float o4[4];
    o4[0] = (xv.x - mean) * rstd * gv.x + bv.x;
    o4[1] = (xv.y - mean) * rstd * gv.y + bv.y;
    o4[2] = (xv.z - mean) * rstd * gv.z + bv.z;
    o4[3] = (xv.w - mean) * rstd * gv.w + bv.w;
    union { bf16 b[4]; uint2 u; } ph, pl;
    #pragma unroll
    for (int k = 0; k < 4; k++) {
        bf16 h = __float2bfloat16(o4[k]);
        ph.b[k] = h;
        pl.b[k] = __float2bfloat16(o4[k] - __bfloat162float(h));
    }
    const size_t off = (size_t)row * E_ + t * 4;
    *(uint2*)(yh + off) = ph.u;
    *(uint2*)(yl + off) = pl.u;
}

// ---------------- HMMA bf16x3 GEMM: C[M,N] = (Ah+Al)[M,K] @ (Bh+Bl)[N,K]^T ----------------
// 128x128 CTA tile, BK=32, 8 warps (2x4), warp tile 64x32, padded smem rows (80B).
#define GK 32
#define RS 40                      // bf16 elems per smem row (32 + 8 pad)
#define MAT_SZ (128 * RS * 2)      // 10240 B
#define STAGE_SZ (4 * MAT_SZ)      // 40960 B
#define GSMEM (2 * STAGE_SZ)       // 81920 B

template <int RELU, int RES, int SPLIT>
__global__ __launch_bounds__(256, 1)
void gemm_hmma(const bf16* __restrict__ Ah, const bf16* __restrict__ Al,
               const bf16* __restrict__ Bh, const bf16* __restrict__ Bl,
               const float* __restrict__ bias, const float* __restrict__ res,
               float* __restrict__ C, bf16* __restrict__ Chi, bf16* __restrict__ Clo,
               int M, int N, int K)
{
    extern __shared__ char smem[];
    const int tid = threadIdx.x;
    const int lane = tid & 31;
    const int wid = tid >> 5;
    const int wm = wid & 1;        // 0..1
    const int wn = wid >> 1;       // 0..3
    const int bm = blockIdx.y * 128;
    const int bn = blockIdx.x * 128;

    float acc[4][4][4];
    #pragma unroll
    for (int a = 0; a < 4; a++)
        #pragma unroll
        for (int b = 0; b < 4; b++)
            #pragma unroll
            for (int c = 0; c < 4; c++) acc[a][b][c] = 0.f;

    // prefetch mapping: idx = tid + rep*256 ; row = idx>>2 (0..127), c16 = idx&3
    const int prow = tid >> 2;
    const int pc = tid & 3;

    const uint32_t sb0 = smem_u32(smem);
    // ldmatrix per-warp bases
    const int arow = wm * 64 + (lane & 15);
    const int brow = wn * 32 + (lane & 15);
    const int acol = (lane >> 4) * 8;

    uint4 v[8];
    const int NK = K / GK;

    // prefetch + store stage 0
    {
        const size_t ko = 0;
        #pragma unroll
        for (int rep = 0; rep < 2; rep++) {
            const int row = prow + rep * 64;
            const size_t ga = (size_t)(bm + row) * K + ko + pc * 8;
            const size_t gb = (size_t)(bn + row) * K + ko + pc * 8;
            v[rep]     = *(const uint4*)(Ah + ga);
            v[2 + rep] = *(const uint4*)(Al + ga);
            v[4 + rep] = *(const uint4*)(Bh + gb);
            v[6 + rep] = *(const uint4*)(Bl + gb);
        }
        char* sb = smem;
        #pragma unroll
        for (int rep = 0; rep < 2; rep++) {
            const int row = prow + rep * 64;
            const uint32_t so = row * (RS * 2) + pc * 16;
            *(uint4*)(sb + so)              = v[rep];
            *(uint4*)(sb + MAT_SZ + so)     = v[2 + rep];
            *(uint4*)(sb + 2 * MAT_SZ + so) = v[4 + rep];
            *(uint4*)(sb + 3 * MAT_SZ + so) = v[6 + rep];
        }
    }
    __syncthreads();

    for (int kt = 0; kt < NK; kt++) {
        const int buf = kt & 1;
        if (kt + 1 < NK) {
            const size_t ko = (size_t)(kt + 1) * GK;
            #pragma unroll
            for (int rep = 0; rep < 2; rep++) {
                const int row = prow + rep * 64;
                const size_t ga = (size_t)(bm + row) * K + ko + pc * 8;
                const size_t gb = (size_t)(bn + row) * K + ko + pc * 8;
                v[rep]     = *(const uint4*)(Ah + ga);
                v[2 + rep] = *(const uint4*)(Al + ga);
                v[4 + rep] = *(const uint4*)(Bh + gb);
                v[6 + rep] = *(const uint4*)(Bl + gb);
            }
        }

        const uint32_t base = sb0 + buf * STAGE_SZ;
        #pragma unroll
        for (int k0 = 0; k0 < 2; k0++) {
            uint32_t ah[4][4], al[4][4];
            #pragma unroll
            for (int mi = 0; mi < 4; mi++) {
                const uint32_t ad = base + (uint32_t)(arow + mi * 16) * (RS * 2) + (k0 * 16 + acol) * 2;
                ldsm_x4(ah[mi], ad);
                ldsm_x4(al[mi], ad + MAT_SZ);
            }
            uint32_t bh[2][4], bl[2][4];
            #pragma unroll
            for (int nb = 0; nb < 2; nb++) {
                const uint32_t bd = base + 2 * MAT_SZ + (uint32_t)(brow + nb * 16) * (RS * 2) + (k0 * 16 + acol) * 2;
                ldsm_x4(bh[nb], bd);
                ldsm_x4(bl[nb], bd + MAT_SZ);
            }
            #pragma unroll
            for (int mi = 0; mi < 4; mi++) {
                #pragma unroll
                for (int nb = 0; nb < 2; nb++) {
                    // n8 tile 0 of this pair: b-frag {r0, r2}; tile 1: {r1, r3}
                    mma_bf16(acc[mi][nb*2],   ah[mi], bh[nb][0], bh[nb][2]);
                    mma_bf16(acc[mi][nb*2+1], ah[mi], bh[nb][1], bh[nb][3]);
                    mma_bf16(acc[mi][nb*2],   ah[mi], bl[nb][0], bl[nb][2]);
                    mma_bf16(acc[mi][nb*2+1], ah[mi], bl[nb][1], bl[nb][3]);
                    mma_bf16(acc[mi][nb*2],   al[mi], bh[nb][0], bh[nb][2]);
                    mma_bf16(acc[mi][nb*2+1], al[mi], bh[nb][1], bh[nb][3]);
                }
            }
        }

        if (kt + 1 < NK) {
            char* sb = smem + (buf ^ 1) * STAGE_SZ;
            #pragma unroll
            for (int rep = 0; rep < 2; rep++) {
                const int row = prow + rep * 64;
                const uint32_t so = row * (RS * 2) + pc * 16;
                *(uint4*)(sb + so)              = v[rep];
                *(uint4*)(sb + MAT_SZ + so)     = v[2 + rep];
                *(uint4*)(sb + 2 * MAT_SZ + so) = v[4 + rep];
                *(uint4*)(sb + 3 * MAT_SZ + so) = v[6 + rep];
            }
        }
        __syncthreads();
    }

    // ---------------- epilogue ----------------
    // fragment (mi, ni): rows bm+wm*64+mi*16+(lane>>2) (+8), cols bn+wn*32+ni*8+(lane&3)*2
    float bv[4][2];
    #pragma unroll
    for (int ni = 0; ni < 4; ni++) {
        const int c0 = bn + wn * 32 + ni * 8 + (lane & 3) * 2;
        bv[ni][0] = bias[c0];
        bv[ni][1] = bias[c0 + 1];
    }
    #pragma unroll
    for (int mi = 0; mi < 4; mi++) {
        const int r0 = bm + wm * 64 + mi * 16 + (lane >> 2);
        #pragma unroll
        for (int ni = 0; ni < 4; ni++) {
            const int c0 = bn + wn * 32 + ni * 8 + (lane & 3) * 2;
            #pragma unroll
            for (int h = 0; h < 2; h++) {
                const int r = r0 + h * 8;
                float v0 = acc[mi][ni][h*2]   + bv[ni][0];
                float v1 = acc[mi][ni][h*2+1] + bv[ni][1];
                if (RELU) { v0 = fmaxf(v0, 0.f); v1 = fmaxf(v1, 0.f); }
                const size_t off = (size_t)r * N + c0;
                if (RES) {
                    float2 rr = *(const float2*)(res + off);
                    v0 += rr.x; v1 += rr.y;
                }
                if (SPLIT) {
                    union { bf16 b[2]; uint32_t u; } ph, pl;
                    bf16 h0 = __float2bfloat16(v0);
                    bf16 h1 = __float2bfloat16(v1);
                    ph.b[0] = h0; ph.b[1] = h1;
                    pl.b[0] = __float2bfloat16(v0 - __bfloat162float(h0));
                    pl.b[1] = __float2bfloat16(v1 - __bfloat162float(h1));
                    *(uint32_t*)(Chi + off) = ph.u;
                    *(uint32_t*)(Clo + off) = pl.u;
                } else {
                    *(float2*)(C + off) = make_float2(v0, v1);
                }
            }
        }
    }
}

// ---------------- Flash attention (fp32), outputs bf16 hi/lo ----------------
#define BQ 128
#define TK 32
__global__ __launch_bounds__(128) void attn_kernel(const float* __restrict__ qkv,
                                                   const float* __restrict__ rel_pos,
                                                   bf16* __restrict__ outh,
                                                   bf16* __restrict__ outl)
{
    __shared__ float Ks[TK][HD_];
    __shared__ float Vs[TK][HD_];
    const int t = threadIdx.x;
    const int q0 = blockIdx.x * BQ;
    const int h = blockIdx.y;
    const int b = blockIdx.z;
    const int i = q0 + t;

    const float* qrow = qkv + ((size_t)(b * S_ + i)) * (3 * E_) + h * HD_;
    float q[HD_];
    #pragma unroll
    for (int d = 0; d < HD_; d += 4) {
        float4 v = *(const float4*)(qrow + d);
        q[d] = v.x * 0.125f; q[d+1] = v.y * 0.125f;
        q[d+2] = v.z * 0.125f; q[d+3] = v.w * 0.125f;
    }
    float o[HD_];
    #pragma unroll
    for (int d = 0; d < HD_; d++) o[d] = 0.f;
    float m = -1e30f, l = 0.f;
    const float* rp = rel_pos + (size_t)h * ML_;
    const int kend = q0 + BQ;

    for (int k0 = 0; k0 < kend; k0 += TK) {
        const float* kbase = qkv + ((size_t)(b * S_ + k0)) * (3 * E_) + E_     + h * HD_;
        const float* vbase = qkv + ((size_t)(b * S_ + k0)) * (3 * E_) + 2 * E_ + h * HD_;
        #pragma unroll
        for (int it = 0; it < (TK * (HD_ / 4)) / 128; it++) {
            const int idx = t + it * 128;
            const int row = idx >> 4;
            const int c4 = idx & 15;
            *(float4*)&Ks[row][c4 * 4] = *(const float4*)(kbase + (size_t)row * (3 * E_) + c4 * 4);
            *(float4*)&Vs[row][c4 * 4] = *(const float4*)(vbase + (size_t)row * (3 * E_) + c4 * 4);
        }
        __syncthreads();

        float sc[TK];
        float tmax = -1e30f;
        for (int j = 0; j < TK; j++) {
            const int kj = k0 + j;
            float s;
            if (kj <= i) {
                float acc2 = 0.f;
                #pragma unroll
                for (int d4 = 0; d4 < HD_ / 4; d4++) {
                    float4 kv = *(const float4*)&Ks[j][d4 * 4];
                    acc2 += q[d4*4] * kv.x + q[d4*4+1] * kv.y + q[d4*4+2] * kv.z + q[d4*4+3] * kv.w;
                }
                s = acc2 + rp[i - kj];
            } else s = -1e30f;
            sc[j] = s;
            tmax = fmaxf(tmax, s);
        }
        const float mnew = fmaxf(m, tmax);
        const float corr = __expf(m - mnew);
        l *= corr;
        #pragma unroll
        for (int d = 0; d < HD_; d++) o[d] *= corr;
        for (int j = 0; j < TK; j++) {
            const float p = __expf(sc[j] - mnew);
            l += p;
            #pragma unroll
            for (int d4 = 0; d4 < HD_ / 4; d4++) {
                float4 vv = *(const float4*)&Vs[j][d4 * 4];
                o[d4*4] += p * vv.x; o[d4*4+1] += p * vv.y;
                o[d4*4+2] += p * vv.z; o[d4*4+3] += p * vv.w;
            }
        }
        m = mnew;
        __syncthreads();
    }

    const float inv = 1.0f / l;
    const size_t off = ((size_t)(b * S_ + i)) * E_ + h * HD_;
    #pragma unroll
    for (int d4 = 0; d4 < HD_ / 4; d4++) {
        union { bf16 b[4]; uint2 u; } ph, pl;
        #pragma unroll
        for (int k = 0; k < 4; k++) {
            float vv = o[d4 * 4 + k] * inv;
            bf16 hh = __float2bfloat16(vv);
            ph.b[k] = hh;
            pl.b[k] = __float2bfloat16(vv - __bfloat162float(hh));
        }
        *(uint2*)(outh + off + d4 * 4) = ph.u;
        *(uint2*)(outl + off + d4 * 4) = pl.u;
    }
}

// ---------------- launch ----------------
extern "C" void kernel_launch(void* const* d_in, const int* in_sizes, int n_in,
                              void* d_out, int out_size)
{
    const float* x         = (const float*)d_in[0];
    const float* rel_pos   = (const float*)d_in[1];
    const float* in_proj_w = (const float*)d_in[2];
    const float* in_proj_b = (const float*)d_in[3];
    const float* out_w     = (const float*)d_in[4];
    const float* out_b     = (const float*)d_in[5];
    const float* w1        = (const float*)d_in[6];
    const float* b1        = (const float*)d_in[7];
    const float* w2        = (const float*)d_in[8];
    const float* b2        = (const float*)d_in[9];
    const float* ln1_g     = (const float*)d_in[10];
    const float* ln1_b     = (const float*)d_in[11];
    const float* ln2_g     = (const float*)d_in[12];
    const float* ln2_b     = (const float*)d_in[13];
    float* out = (float*)d_out;

    bf16 *wqh, *wql, *woh, *wol, *w1h, *w1l, *w2h, *w2l;
    bf16 *xnh, *xnl, *aoh, *aol, *xmh, *xml, *h1h, *h1l;
    float *qkv, *x1;
    cudaGetSymbolAddress((void**)&wqh, g_wqh); cudaGetSymbolAddress((void**)&wql, g_wql);
    cudaGetSymbolAddress((void**)&woh, g_woh); cudaGetSymbolAddress((void**)&wol, g_wol);
    cudaGetSymbolAddress((void**)&w1h, g_w1h); cudaGetSymbolAddress((void**)&w1l, g_w1l);
    cudaGetSymbolAddress((void**)&w2h, g_w2h); cudaGetSymbolAddress((void**)&w2l, g_w2l);
    cudaGetSymbolAddress((void**)&xnh, g_xnh); cudaGetSymbolAddress((void**)&xnl, g_xnl);
    cudaGetSymbolAddress((void**)&aoh, g_aoh); cudaGetSymbolAddress((void**)&aol, g_aol);
    cudaGetSymbolAddress((void**)&xmh, g_xmh); cudaGetSymbolAddress((void**)&xml, g_xml);
    cudaGetSymbolAddress((void**)&h1h, g_h1h); cudaGetSymbolAddress((void**)&h1l, g_h1l);
    cudaGetSymbolAddress((void**)&qkv, g_qkv); cudaGetSymbolAddress((void**)&x1,  g_x1);

    cudaFuncSetAttribute(gemm_hmma<0,0,0>, cudaFuncAttributeMaxDynamicSharedMemorySize, GSMEM);
    cudaFuncSetAttribute(gemm_hmma<0,1,0>, cudaFuncAttributeMaxDynamicSharedMemorySize, GSMEM);
    cudaFuncSetAttribute(gemm_hmma<1,0,1>, cudaFuncAttributeMaxDynamicSharedMemorySize, GSMEM);

    // weight splits
    cvt_bf<<<(3*E_*E_/4 + 255)/256, 256>>>(in_proj_w, wqh, wql, 3*E_*E_/4);
    cvt_bf<<<(E_*E_/4 + 255)/256, 256>>>(out_w, woh, wol, E_*E_/4);
    cvt_bf<<<(4*E_*E_/4 + 255)/256, 256>>>(w1, w1h, w1l, 4*E_*E_/4);
    cvt_bf<<<(4*E_*E_/4 + 255)/256, 256>>>(w2, w2h, w2l, 4*E_*E_/4);

    // 1) LN1 -> xn hi/lo
    ln_bf<<<MR, 256>>>(x, ln1_g, ln1_b, xnh, xnl);
    // 2) QKV: [4096,3072] fp32
    gemm_hmma<0,0,0><<<dim3(3*E_/128, MR/128), 256, GSMEM>>>(
        xnh, xnl, wqh, wql, in_proj_b, nullptr, qkv, nullptr, nullptr, MR, 3*E_, E_);
    // 3) attention -> ao hi/lo
    attn_kernel<<<dim3(S_/BQ, H_, B_), 128>>>(qkv, rel_pos, aoh, aol);
    // 4) out-proj + residual -> x1 fp32
    gemm_hmma<0,1,0><<<dim3(E_/128, MR/128), 256, GSMEM>>>(
        aoh, aol, woh, wol, out_b, x, x1, nullptr, nullptr, MR, E_, E_);
    // 5) LN2 -> xm hi/lo
    ln_bf<<<MR, 256>>>(x1, ln2_g, ln2_b, xmh, xml);
    // 6) MLP up + ReLU -> h1 hi/lo
    gemm_hmma<1,0,1><<<dim3(4*E_/128, MR/128), 256, GSMEM>>>(
        xmh, xml, w1h, w1l, b1, nullptr, nullptr, h1h, h1l, MR, 4*E_, E_);
    // 7) MLP down + residual -> out fp32
    gemm_hmma<0,1,0><<<dim3(E_/128, MR/128), 256, GSMEM>>>(
        h1h, h1l, w2h, w2l, b2, x1, out, nullptr, nullptr, MR, E_, 4*E_);
}

// round 4
// speedup vs baseline: 2.6523x; 1.3800x over previous
#include <cuda_runtime.h>
#include <cuda_bf16.h>
#include <cstdint>
#include <cstddef>

// Problem constants
#define B_  4
#define S_  1024
#define E_  1024
#define H_  16
#define HD_ 64
#define ML_ 2048
#define MR  4096   // B*S

typedef __nv_bfloat16 bf16;

// ---------------- static scratch ----------------
__device__ bf16  g_wqh[3*E_*E_], g_wql[3*E_*E_];
__device__ bf16  g_woh[E_*E_],   g_wol[E_*E_];
__device__ bf16  g_w1h[4*E_*E_], g_w1l[4*E_*E_];
__device__ bf16  g_w2h[4*E_*E_], g_w2l[4*E_*E_];
__device__ bf16  g_xnh[MR*E_],   g_xnl[MR*E_];
__device__ bf16  g_qkvh[(size_t)MR*3*E_], g_qkvl[(size_t)MR*3*E_];
__device__ bf16  g_aoh[MR*E_],   g_aol[MR*E_];
__device__ float g_x1 [MR*E_];
__device__ bf16  g_xmh[MR*E_],   g_xml[MR*E_];
__device__ bf16  g_h1h[(size_t)MR*4*E_], g_h1l[(size_t)MR*4*E_];

// ---------------- helpers ----------------
__device__ __forceinline__ uint32_t smem_u32(const void* p) {
    uint32_t a;
    asm("{ .reg .u64 t; cvta.to.shared.u64 t, %1; cvt.u32.u64 %0, t; }" : "=r"(a) : "l"(p));
    return a;
}
__device__ __forceinline__ void ldsm_x4(uint32_t* r, uint32_t addr) {
    asm volatile("ldmatrix.sync.aligned.m8n8.x4.shared.b16 {%0,%1,%2,%3}, [%4];"
        : "=r"(r[0]), "=r"(r[1]), "=r"(r[2]), "=r"(r[3]) : "r"(addr));
}
__device__ __forceinline__ void ldsm_x4_t(uint32_t* r, uint32_t addr) {
    asm volatile("ldmatrix.sync.aligned.m8n8.x4.trans.shared.b16 {%0,%1,%2,%3}, [%4];"
        : "=r"(r[0]), "=r"(r[1]), "=r"(r[2]), "=r"(r[3]) : "r"(addr));
}
__device__ __forceinline__ void mma_bf16(float* d, const uint32_t* a, uint32_t b0, uint32_t b1) {
    asm volatile("mma.sync.aligned.m16n8k16.row.col.f32.bf16.bf16.f32 "
        "{%0,%1,%2,%3},{%4,%5,%6,%7},{%8,%9},{%0,%1,%2,%3};"
        : "+f"(d[0]), "+f"(d[1]), "+f"(d[2]), "+f"(d[3])
        : "r"(a[0]), "r"(a[1]), "r"(a[2]), "r"(a[3]), "r"(b0), "r"(b1));
}
__device__ __forceinline__ uint32_t pack2(bf16 a, bf16 b) {
    union { bf16 h[2]; uint32_t u; } t;
    t.h[0] = a; t.h[1] = b;
    return t.u;
}

// ---------------- weight split conversion ----------------
__global__ __launch_bounds__(256) void cvt_bf(const float* __restrict__ in,
                                              bf16* __restrict__ hi, bf16* __restrict__ lo, int n4)
{
    int i = blockIdx.x * blockDim.x + threadIdx.x;
    if (i >= n4) return;
    float4 v = ((const float4*)in)[i];
    union { bf16 b[4]; uint2 u; } ph, pl;
    float vv[4] = { v.x, v.y, v.z, v.w };
    #pragma unroll
    for (int k = 0; k < 4; k++) {
        bf16 h = __float2bfloat16(vv[k]);
        ph.b[k] = h;
        pl.b[k] = __float2bfloat16(vv[k] - __bfloat162float(h));
    }
    ((uint2*)hi)[i] = ph.u;
    ((uint2*)lo)[i] = pl.u;
}

// ---------------- LayerNorm -> bf16 hi/lo ----------------
__global__ __launch_bounds__(256) void ln_bf(const float* __restrict__ x,
                                             const float* __restrict__ gamma,
                                             const float* __restrict__ beta,
                                             bf16* __restrict__ yh, bf16* __restrict__ yl)
{
    const int row = blockIdx.x;
    const int t = threadIdx.x;
    const float* xr = x + (size_t)row * E_;
    float4 xv = *(const float4*)(xr + t * 4);
    float s = xv.x + xv.y + xv.z + xv.w;
    float sq = xv.x*xv.x + xv.y*xv.y + xv.z*xv.z + xv.w*xv.w;
    #pragma unroll
    for (int o = 16; o > 0; o >>= 1) {
        s  += __shfl_down_sync(0xffffffffu, s, o);
        sq += __shfl_down_sync(0xffffffffu, sq, o);
    }
    __shared__ float sa[8], sb[8];
    const int w = t >> 5, lane = t & 31;
    if (lane == 0) { sa[w] = s; sb[w] = sq; }
    __syncthreads();
    float ts = 0.f, tq = 0.f;
    #pragma unroll
    for (int k = 0; k < 8; k++) { ts += sa[k]; tq += sb[k]; }
    const float mean = ts * (1.0f / E_);
    const float var = tq * (1.0f / E_) - mean * mean;
    const float rstd = rsqrtf(var + 1e-5f);
    float4 gv = *(const float4*)(gamma + t * 4);
    float4 bv = *(const float4*)(beta + t * 4);
    float o4[4];
    o4[0] = (xv.x - mean) * rstd * gv.x + bv.x;
    o4[1] = (xv.y - mean) * rstd * gv.y + bv.y;
    o4[2] = (xv.z - mean) * rstd * gv.z + bv.z;
    o4[3] = (xv.w - mean) * rstd * gv.w + bv.w;
    union { bf16 b[4]; uint2 u; } ph, pl;
    #pragma unroll
    for (int k = 0; k < 4; k++) {
        bf16 h = __float2bfloat16(o4[k]);
        ph.b[k] = h;
        pl.b[k] = __float2bfloat16(o4[k] - __bfloat162float(h));
    }
    const size_t off = (size_t)row * E_ + t * 4;
    *(uint2*)(yh + off) = ph.u;
    *(uint2*)(yl + off) = pl.u;
}

// ---------------- HMMA bf16x3 GEMM (as validated in R3) ----------------
#define GK 32
#define RS 40
#define MAT_SZ (128 * RS * 2)
#define STAGE_SZ (4 * MAT_SZ)
#define GSMEM (2 * STAGE_SZ)

template <int RELU, int RES, int SPLIT>
__global__ __launch_bounds__(256, 1)
void gemm_hmma(const bf16* __restrict__ Ah, const bf16* __restrict__ Al,
               const bf16* __restrict__ Bh, const bf16* __restrict__ Bl,
               const float* __restrict__ bias, const float* __restrict__ res,
               float* __restrict__ C, bf16* __restrict__ Chi, bf16* __restrict__ Clo,
               int M, int N, int K)
{
    extern __shared__ char smem[];
    const int tid = threadIdx.x;
    const int lane = tid & 31;
    const int wid = tid >> 5;
    const int wm = wid & 1;
    const int wn = wid >> 1;
    const int bm = blockIdx.y * 128;
    const int bn = blockIdx.x * 128;

    float acc[4][4][4];
    #pragma unroll
    for (int a = 0; a < 4; a++)
        #pragma unroll
        for (int b = 0; b < 4; b++)
            #pragma unroll
            for (int c = 0; c < 4; c++) acc[a][b][c] = 0.f;

    const int prow = tid >> 2;
    const int pc = tid & 3;
    const uint32_t sb0 = smem_u32(smem);
    const int arow = wm * 64 + (lane & 15);
    const int brow = wn * 32 + (lane & 15);
    const int acol = (lane >> 4) * 8;

    uint4 v[8];
    const int NK = K / GK;

    {
        #pragma unroll
        for (int rep = 0; rep < 2; rep++) {
            const int row = prow + rep * 64;
            const size_t ga = (size_t)(bm + row) * K + pc * 8;
            const size_t gb = (size_t)(bn + row) * K + pc * 8;
            v[rep]     = *(const uint4*)(Ah + ga);
            v[2 + rep] = *(const uint4*)(Al + ga);
            v[4 + rep] = *(const uint4*)(Bh + gb);
            v[6 + rep] = *(const uint4*)(Bl + gb);
        }
        char* sb = smem;
        #pragma unroll
        for (int rep = 0; rep < 2; rep++) {
            const int row = prow + rep * 64;
            const uint32_t so = row * (RS * 2) + pc * 16;
            *(uint4*)(sb + so)              = v[rep];
            *(uint4*)(sb + MAT_SZ + so)     = v[2 + rep];
            *(uint4*)(sb + 2 * MAT_SZ + so) = v[4 + rep];
            *(uint4*)(sb + 3 * MAT_SZ + so) = v[6 + rep];
        }
    }
    __syncthreads();

    for (int kt = 0; kt < NK; kt++) {
        const int buf = kt & 1;
        if (kt + 1 < NK) {
            const size_t ko = (size_t)(kt + 1) * GK;
            #pragma unroll
            for (int rep = 0; rep < 2; rep++) {
                const int row = prow + rep * 64;
                const size_t ga = (size_t)(bm + row) * K + ko + pc * 8;
                const size_t gb = (size_t)(bn + row) * K + ko + pc * 8;
                v[rep]     = *(const uint4*)(Ah + ga);
                v[2 + rep] = *(const uint4*)(Al + ga);
                v[4 + rep] = *(const uint4*)(Bh + gb);
                v[6 + rep] = *(const uint4*)(Bl + gb);
            }
        }

        const uint32_t base = sb0 + buf * STAGE_SZ;
        #pragma unroll
        for (int k0 = 0; k0 < 2; k0++) {
            uint32_t ah[4][4], al[4][4];
            #pragma unroll
            for (int mi = 0; mi < 4; mi++) {
                const uint32_t ad = base + (uint32_t)(arow + mi * 16) * (RS * 2) + (k0 * 16 + acol) * 2;
                ldsm_x4(ah[mi], ad);
                ldsm_x4(al[mi], ad + MAT_SZ);
            }
            uint32_t bh[2][4], bl[2][4];
            #pragma unroll
            for (int nb = 0; nb < 2; nb++) {
                const uint32_t bd = base + 2 * MAT_SZ + (uint32_t)(brow + nb * 16) * (RS * 2) + (k0 * 16 + acol) * 2;
                ldsm_x4(bh[nb], bd);
                ldsm_x4(bl[nb], bd + MAT_SZ);
            }
            #pragma unroll
            for (int mi = 0; mi < 4; mi++) {
                #pragma unroll
                for (int nb = 0; nb < 2; nb++) {
                    mma_bf16(acc[mi][nb*2],   ah[mi], bh[nb][0], bh[nb][2]);
                    mma_bf16(acc[mi][nb*2+1], ah[mi], bh[nb][1], bh[nb][3]);
                    mma_bf16(acc[mi][nb*2],   ah[mi], bl[nb][0], bl[nb][2]);
                    mma_bf16(acc[mi][nb*2+1], ah[mi], bl[nb][1], bl[nb][3]);
                    mma_bf16(acc[mi][nb*2],   al[mi], bh[nb][0], bh[nb][2]);
                    mma_bf16(acc[mi][nb*2+1], al[mi], bh[nb][1], bh[nb][3]);
                }
            }
        }

        if (kt + 1 < NK) {
            char* sb = smem + (buf ^ 1) * STAGE_SZ;
            #pragma unroll
            for (int rep = 0; rep < 2; rep++) {
                const int row = prow + rep * 64;
                const uint32_t so = row * (RS * 2) + pc * 16;
                *(uint4*)(sb + so)              = v[rep];
                *(uint4*)(sb + MAT_SZ + so)     = v[2 + rep];
                *(uint4*)(sb + 2 * MAT_SZ + so) = v[4 + rep];
                *(uint4*)(sb + 3 * MAT_SZ + so) = v[6 + rep];
            }
        }
        __syncthreads();
    }

    float bv[4][2];
    #pragma unroll
    for (int ni = 0; ni < 4; ni++) {
        const int c0 = bn + wn * 32 + ni * 8 + (lane & 3) * 2;
        bv[ni][0] = bias[c0];
        bv[ni][1] = bias[c0 + 1];
    }
    #pragma unroll
    for (int mi = 0; mi < 4; mi++) {
        const int r0 = bm + wm * 64 + mi * 16 + (lane >> 2);
        #pragma unroll
        for (int ni = 0; ni < 4; ni++) {
            const int c0 = bn + wn * 32 + ni * 8 + (lane & 3) * 2;
            #pragma unroll
            for (int h = 0; h < 2; h++) {
                const int r = r0 + h * 8;
                float v0 = acc[mi][ni][h*2]   + bv[ni][0];
                float v1 = acc[mi][ni][h*2+1] + bv[ni][1];
                if (RELU) { v0 = fmaxf(v0, 0.f); v1 = fmaxf(v1, 0.f); }
                const size_t off = (size_t)r * N + c0;
                if (RES) {
                    float2 rr = *(const float2*)(res + off);
                    v0 += rr.x; v1 += rr.y;
                }
                if (SPLIT) {
                    bf16 h0 = __float2bfloat16(v0);
                    bf16 h1 = __float2bfloat16(v1);
                    *(uint32_t*)(Chi + off) = pack2(h0, h1);
                    *(uint32_t*)(Clo + off) = pack2(__float2bfloat16(v0 - __bfloat162float(h0)),
                                                    __float2bfloat16(v1 - __bfloat162float(h1)));
                } else {
                    *(float2*)(C + off) = make_float2(v0, v1);
                }
            }
        }
    }
}

// ---------------- HMMA flash attention ----------------
// CTA = (qtile 64, head, batch); 4 warps x 16 q rows. bf16x3 for QK^T and PV.
#define ARS 72                     // bf16 elems per smem row (64 + 8 pad) -> 144B
#define ATILE (64 * ARS * 2)       // 9216 B per matrix
#define A_QH 0
#define A_QL (ATILE)
#define A_KH (2*ATILE)
#define A_KL (3*ATILE)
#define A_VH (4*ATILE)
#define A_VL (5*ATILE)
#define A_BIAS (6*ATILE)
#define ASMEM (6*ATILE + 512)

__global__ __launch_bounds__(128)
void attn_mma(const bf16* __restrict__ qkvh, const bf16* __restrict__ qkvl,
              const float* __restrict__ rel_pos,
              bf16* __restrict__ outh, bf16* __restrict__ outl)
{
    extern __shared__ char smem[];
    const uint32_t sb = smem_u32(smem);
    const int tid = threadIdx.x;
    const int lane = tid & 31;
    const int w = tid >> 5;
    const int q0 = blockIdx.x * 64;
    const int h = blockIdx.y;
    const int b = blockIdx.z;

    const int rl = lane >> 2;        // 0..7
    const int cl = (lane & 3) * 2;   // 0,2,4,6

    // load Q tile (64 x 64) hi/lo, scaled by 0.125
    {
        const __nv_bfloat162 sc = __floats2bfloat162_rn(0.125f, 0.125f);
        #pragma unroll
        for (int p = 0; p < 4; p++) {
            const int chunk = tid + p * 128;     // 512 chunks
            const int row = chunk >> 3;
            const int c16 = chunk & 7;
            const size_t ga = (size_t)(b * S_ + q0 + row) * (3 * E_) + h * 64 + c16 * 8;
            uint4 vh = *(const uint4*)(qkvh + ga);
            uint4 vl = *(const uint4*)(qkvl + ga);
            __nv_bfloat162* ph = (__nv_bfloat162*)&vh;
            __nv_bfloat162* pl = (__nv_bfloat162*)&vl;
            #pragma unroll
            for (int k = 0; k < 4; k++) { ph[k] = __hmul2(ph[k], sc); pl[k] = __hmul2(pl[k], sc); }
            const uint32_t so = row * (ARS * 2) + c16 * 16;
            *(uint4*)(smem + A_QH + so) = vh;
            *(uint4*)(smem + A_QL + so) = vl;
        }
    }

    float o[8][4];
    #pragma unroll
    for (int t = 0; t < 8; t++)
        #pragma unroll
        for (int e = 0; e < 4; e++) o[t][e] = 0.f;
    float m0 = -1e30f, m1 = -1e30f, l0 = 0.f, l1 = 0.f;

    const float* rp = rel_pos + (size_t)h * ML_;

    for (int k0 = 0; k0 <= q0; k0 += 64) {
        __syncthreads();   // protect previous tile's smem reads
        // load K/V tiles (64 x 64) hi/lo
        #pragma unroll
        for (int p = 0; p < 4; p++) {
            const int chunk = tid + p * 128;
            const int row = chunk >> 3;
            const int c16 = chunk & 7;
            const size_t gk = (size_t)(b * S_ + k0 + row) * (3 * E_) + E_ + h * 64 + c16 * 8;
            const size_t gv = gk + E_;
            const uint32_t so = row * (ARS * 2) + c16 * 16;
            *(uint4*)(smem + A_KH + so) = *(const uint4*)(qkvh + gk);
            *(uint4*)(smem + A_KL + so) = *(const uint4*)(qkvl + gk);
            *(uint4*)(smem + A_VH + so) = *(const uint4*)(qkvh + gv);
            *(uint4*)(smem + A_VL + so) = *(const uint4*)(qkvl + gv);
        }
        // stage bias values rp[q0-k0-63 .. q0-k0+63]
        if (tid < 127) {
            const int idx = q0 - k0 - 63 + tid;
            *(float*)(smem + A_BIAS + tid * 4) = (idx >= 0) ? rp[idx] : 0.f;
        }
        __syncthreads();

        // S = Q K^T (3-term)
        float s[8][4];
        #pragma unroll
        for (int t = 0; t < 8; t++)
            #pragma unroll
            for (int e = 0; e < 4; e++) s[t][e] = 0.f;

        #pragma unroll
        for (int d4 = 0; d4 < 4; d4++) {
            uint32_t ah[4], al[4];
            const uint32_t qa = sb + A_QH + (uint32_t)(w * 16 + (lane & 15)) * (ARS * 2) + (d4 * 16 + (lane >> 4) * 8) * 2;
            ldsm_x4(ah, qa);
            ldsm_x4(al, qa + ATILE);
            #pragma unroll
            for (int nb = 0; nb < 4; nb++) {
                uint32_t kh[4], kl[4];
                const uint32_t ka = sb + A_KH + (uint32_t)(nb * 16 + (lane & 15)) * (ARS * 2) + (d4 * 16 + (lane >> 4) * 8) * 2;
                ldsm_x4(kh, ka);
                ldsm_x4(kl, ka + ATILE);
                mma_bf16(s[nb*2],   ah, kh[0], kh[2]);
                mma_bf16(s[nb*2+1], ah, kh[1], kh[3]);
                mma_bf16(s[nb*2],   ah, kl[0], kl[2]);
                mma_bf16(s[nb*2+1], ah, kl[1], kl[3]);
                mma_bf16(s[nb*2],   al, kh[0], kh[2]);
                mma_bf16(s[nb*2+1], al, kh[1], kh[3]);
            }
        }

        // bias + mask + row max
        const bool diag = (k0 == q0);
        const int i0 = w * 16 + rl;       // local row (0..63)
        const int i1 = i0 + 8;
        float tmax0 = -1e30f, tmax1 = -1e30f;
        #pragma unroll
        for (int t = 0; t < 8; t++) {
            const int c0 = t * 8 + cl;
            #pragma unroll
            for (int e = 0; e < 4; e++) {
                const int irow = (e < 2) ? i0 : i1;
                const int c = c0 + (e & 1);
                float val = s[t][e] + *(const float*)(smem + A_BIAS + (63 + irow - c) * 4);
                if (diag && c > irow) val = -1e30f;
                s[t][e] = val;
                if (e < 2) tmax0 = fmaxf(tmax0, val);
                else       tmax1 = fmaxf(tmax1, val);
            }
        }
        #pragma unroll
        for (int xo = 1; xo <= 2; xo <<= 1) {
            tmax0 = fmaxf(tmax0, __shfl_xor_sync(0xffffffffu, tmax0, xo));
            tmax1 = fmaxf(tmax1, __shfl_xor_sync(0xffffffffu, tmax1, xo));
        }
        const float mn0 = fmaxf(m0, tmax0);
        const float mn1 = fmaxf(m1, tmax1);
        const float corr0 = __expf(m0 - mn0);
        const float corr1 = __expf(m1 - mn1);
        m0 = mn0; m1 = mn1;

        float rs0 = 0.f, rs1 = 0.f;
        #pragma unroll
        for (int t = 0; t < 8; t++) {
            s[t][0] = __expf(s[t][0] - mn0);
            s[t][1] = __expf(s[t][1] - mn0);
            s[t][2] = __expf(s[t][2] - mn1);
            s[t][3] = __expf(s[t][3] - mn1);
            rs0 += s[t][0] + s[t][1];
            rs1 += s[t][2] + s[t][3];
        }
        #pragma unroll
        for (int xo = 1; xo <= 2; xo <<= 1) {
            rs0 += __shfl_xor_sync(0xffffffffu, rs0, xo);
            rs1 += __shfl_xor_sync(0xffffffffu, rs1, xo);
        }
        l0 = l0 * corr0 + rs0;
        l1 = l1 * corr1 + rs1;
        #pragma unroll
        for (int t = 0; t < 8; t++) {
            o[t][0] *= corr0; o[t][1] *= corr0;
            o[t][2] *= corr1; o[t][3] *= corr1;
        }

        // P V (3-term): A frags from s, B frags via ldmatrix.trans of V
        #pragma unroll
        for (int kb = 0; kb < 4; kb++) {
            uint32_t pah[4], pal[4];
            {
                const float* sA = s[2*kb];
                const float* sB = s[2*kb+1];
                bf16 hA0 = __float2bfloat16(sA[0]), hA1 = __float2bfloat16(sA[1]);
                bf16 hA2 = __float2bfloat16(sA[2]), hA3 = __float2bfloat16(sA[3]);
                bf16 hB0 = __float2bfloat16(sB[0]), hB1 = __float2bfloat16(sB[1]);
                bf16 hB2 = __float2bfloat16(sB[2]), hB3 = __float2bfloat16(sB[3]);
                pah[0] = pack2(hA0, hA1);
                pah[1] = pack2(hA2, hA3);
                pah[2] = pack2(hB0, hB1);
                pah[3] = pack2(hB2, hB3);
                pal[0] = pack2(__float2bfloat16(sA[0] - __bfloat162float(hA0)),
                               __float2bfloat16(sA[1] - __bfloat162float(hA1)));
                pal[1] = pack2(__float2bfloat16(sA[2] - __bfloat162float(hA2)),
                               __float2bfloat16(sA[3] - __bfloat162float(hA3)));
                pal[2] = pack2(__float2bfloat16(sB[0] - __bfloat162float(hB0)),
                               __float2bfloat16(sB[1] - __bfloat162float(hB1)));
                pal[3] = pack2(__float2bfloat16(sB[2] - __bfloat162float(hB2)),
                               __float2bfloat16(sB[3] - __bfloat162float(hB3)));
            }
            #pragma unroll
            for (int nb = 0; nb < 4; nb++) {
                uint32_t vh[4], vl[4];
                const uint32_t va = sb + A_VH + (uint32_t)(kb * 16 + (lane & 15)) * (ARS * 2) + (nb * 16 + (lane >> 4) * 8) * 2;
                ldsm_x4_t(vh, va);
                ldsm_x4_t(vl, va + ATILE);
                // trans pairing: n8 tile 2nb: {r0,r1}; tile 2nb+1: {r2,r3}
                mma_bf16(o[nb*2],   pah, vh[0], vh[1]);
                mma_bf16(o[nb*2+1], pah, vh[2], vh[3]);
                mma_bf16(o[nb*2],   pah, vl[0], vl[1]);
                mma_bf16(o[nb*2+1], pah, vl[2], vl[3]);
                mma_bf16(o[nb*2],   pal, vh[0], vh[1]);
                mma_bf16(o[nb*2+1], pal, vh[2], vh[3]);
            }
        }
    }

    // epilogue
    const float inv0 = 1.0f / l0;
    const float inv1 = 1.0f / l1;
    const int tok0 = b * S_ + q0 + w * 16 + rl;
    const int tok1 = tok0 + 8;
    #pragma unroll
    for (int t = 0; t < 8; t++) {
        const int col = h * 64 + t * 8 + cl;
        float v0 = o[t][0] * inv0, v1 = o[t][1] * inv0;
        float v2 = o[t][2] * inv1, v3 = o[t][3] * inv1;
        bf16 h0 = __float2bfloat16(v0), h1 = __float2bfloat16(v1);
        bf16 h2 = __float2bfloat16(v2), h3 = __float2bfloat16(v3);
        const size_t o0 = (size_t)tok0 * E_ + col;
        const size_t o1 = (size_t)tok1 * E_ + col;
        *(uint32_t*)(outh + o0) = pack2(h0, h1);
        *(uint32_t*)(outl + o0) = pack2(__float2bfloat16(v0 - __bfloat162float(h0)),
                                        __float2bfloat16(v1 - __bfloat162float(h1)));
        *(uint32_t*)(outh + o1) = pack2(h2, h3);
        *(uint32_t*)(outl + o1) = pack2(__float2bfloat16(v2 - __bfloat162float(h2)),
                                        __float2bfloat16(v3 - __bfloat162float(h3)));
    }
}

// ---------------- launch ----------------
extern "C" void kernel_launch(void* const* d_in, const int* in_sizes, int n_in,
                              void* d_out, int out_size)
{
    const float* x         = (const float*)d_in[0];
    const float* rel_pos   = (const float*)d_in[1];
    const float* in_proj_w = (const float*)d_in[2];
    const float* in_proj_b = (const float*)d_in[3];
    const float* out_w     = (const float*)d_in[4];
    const float* out_b     = (const float*)d_in[5];
    const float* w1        = (const float*)d_in[6];
    const float* b1        = (const float*)d_in[7];
    const float* w2        = (const float*)d_in[8];
    const float* b2        = (const float*)d_in[9];
    const float* ln1_g     = (const float*)d_in[10];
    const float* ln1_b     = (const float*)d_in[11];
    const float* ln2_g     = (const float*)d_in[12];
    const float* ln2_b     = (const float*)d_in[13];
    float* out = (float*)d_out;

    bf16 *wqh, *wql, *woh, *wol, *w1h, *w1l, *w2h, *w2l;
    bf16 *xnh, *xnl, *aoh, *aol, *xmh, *xml, *h1h, *h1l, *qkvh, *qkvl;
    float *x1;
    cudaGetSymbolAddress((void**)&wqh, g_wqh); cudaGetSymbolAddress((void**)&wql, g_wql);
    cudaGetSymbolAddress((void**)&woh, g_woh); cudaGetSymbolAddress((void**)&wol, g_wol);
    cudaGetSymbolAddress((void**)&w1h, g_w1h); cudaGetSymbolAddress((void**)&w1l, g_w1l);
    cudaGetSymbolAddress((void**)&w2h, g_w2h); cudaGetSymbolAddress((void**)&w2l, g_w2l);
    cudaGetSymbolAddress((void**)&xnh, g_xnh); cudaGetSymbolAddress((void**)&xnl, g_xnl);
    cudaGetSymbolAddress((void**)&aoh, g_aoh); cudaGetSymbolAddress((void**)&aol, g_aol);
    cudaGetSymbolAddress((void**)&xmh, g_xmh); cudaGetSymbolAddress((void**)&xml, g_xml);
    cudaGetSymbolAddress((void**)&h1h, g_h1h); cudaGetSymbolAddress((void**)&h1l, g_h1l);
    cudaGetSymbolAddress((void**)&qkvh, g_qkvh); cudaGetSymbolAddress((void**)&qkvl, g_qkvl);
    cudaGetSymbolAddress((void**)&x1, g_x1);

    cudaFuncSetAttribute(gemm_hmma<0,0,1>, cudaFuncAttributeMaxDynamicSharedMemorySize, GSMEM);
    cudaFuncSetAttribute(gemm_hmma<0,1,0>, cudaFuncAttributeMaxDynamicSharedMemorySize, GSMEM);
    cudaFuncSetAttribute(gemm_hmma<1,0,1>, cudaFuncAttributeMaxDynamicSharedMemorySize, GSMEM);
    cudaFuncSetAttribute(attn_mma, cudaFuncAttributeMaxDynamicSharedMemorySize, ASMEM);

    // weight splits
    cvt_bf<<<(3*E_*E_/4 + 255)/256, 256>>>(in_proj_w, wqh, wql, 3*E_*E_/4);
    cvt_bf<<<(E_*E_/4 + 255)/256, 256>>>(out_w, woh, wol, E_*E_/4);
    cvt_bf<<<(4*E_*E_/4 + 255)/256, 256>>>(w1, w1h, w1l, 4*E_*E_/4);
    cvt_bf<<<(4*E_*E_/4 + 255)/256, 256>>>(w2, w2h, w2l, 4*E_*E_/4);

    // 1) LN1 -> xn hi/lo
    ln_bf<<<MR, 256>>>(x, ln1_g, ln1_b, xnh, xnl);
    // 2) QKV -> bf16 hi/lo [token][3E]
    gemm_hmma<0,0,1><<<dim3(3*E_/128, MR/128), 256, GSMEM>>>(
        xnh, xnl, wqh, wql, in_proj_b, nullptr, nullptr, qkvh, qkvl, MR, 3*E_, E_);
    // 3) attention -> ao hi/lo
    attn_mma<<<dim3(S_/64, H_, B_), 128, ASMEM>>>(qkvh, qkvl, rel_pos, aoh, aol);
    // 4) out-proj + residual -> x1 fp32
    gemm_hmma<0,1,0><<<dim3(E_/128, MR/128), 256, GSMEM>>>(
        aoh, aol, woh, wol, out_b, x, x1, nullptr, nullptr, MR, E_, E_);
    // 5) LN2 -> xm hi/lo
    ln_bf<<<MR, 256>>>(x1, ln2_g, ln2_b, xmh, xml);
    // 6) MLP up + ReLU -> h1 hi/lo
    gemm_hmma<1,0,1><<<dim3(4*E_/128, MR/128), 256, GSMEM>>>(
        xmh, xml, w1h, w1l, b1, nullptr, nullptr, h1h, h1l, MR, 4*E_, E_);
    // 7) MLP down + residual -> out fp32
    gemm_hmma<0,1,0><<<dim3(E_/128, MR/128), 256, GSMEM>>>(
        h1h, h1l, w2h, w2l, b2, x1, out, nullptr, nullptr, MR, E_, 4*E_);
}

// round 5
// speedup vs baseline: 3.2465x; 1.2240x over previous
#include <cuda_runtime.h>
#include <cuda_bf16.h>
#include <cuda_fp16.h>
#include <cstdint>
#include <cstddef>

// Problem constants
#define B_  4
#define S_  1024
#define E_  1024
#define H_  16
#define HD_ 64
#define ML_ 2048
#define MR  4096   // B*S

typedef __nv_bfloat16 bf16;
typedef __half hf;

// ---------------- static scratch ----------------
__device__ hf    g_wq[3*E_*E_];
__device__ hf    g_wo[E_*E_];
__device__ hf    g_w1[4*E_*E_];
__device__ hf    g_w2[4*E_*E_];
__device__ hf    g_xnh[MR*E_],   g_xnl[MR*E_];
__device__ bf16  g_qkvh[(size_t)MR*3*E_], g_qkvl[(size_t)MR*3*E_];
__device__ hf    g_aoh[MR*E_],   g_aol[MR*E_];
__device__ float g_x1 [MR*E_];
__device__ hf    g_xmh[MR*E_],   g_xml[MR*E_];
__device__ hf    g_h1h[(size_t)MR*4*E_], g_h1l[(size_t)MR*4*E_];

// ---------------- helpers ----------------
__device__ __forceinline__ uint32_t smem_u32(const void* p) {
    uint32_t a;
    asm("{ .reg .u64 t; cvta.to.shared.u64 t, %1; cvt.u32.u64 %0, t; }" : "=r"(a) : "l"(p));
    return a;
}
__device__ __forceinline__ void ldsm_x4(uint32_t* r, uint32_t addr) {
    asm volatile("ldmatrix.sync.aligned.m8n8.x4.shared.b16 {%0,%1,%2,%3}, [%4];"
        : "=r"(r[0]), "=r"(r[1]), "=r"(r[2]), "=r"(r[3]) : "r"(addr));
}
__device__ __forceinline__ void ldsm_x4_t(uint32_t* r, uint32_t addr) {
    asm volatile("ldmatrix.sync.aligned.m8n8.x4.trans.shared.b16 {%0,%1,%2,%3}, [%4];"
        : "=r"(r[0]), "=r"(r[1]), "=r"(r[2]), "=r"(r[3]) : "r"(addr));
}
__device__ __forceinline__ void mma_bf16(float* d, const uint32_t* a, uint32_t b0, uint32_t b1) {
    asm volatile("mma.sync.aligned.m16n8k16.row.col.f32.bf16.bf16.f32 "
        "{%0,%1,%2,%3},{%4,%5,%6,%7},{%8,%9},{%0,%1,%2,%3};"
        : "+f"(d[0]), "+f"(d[1]), "+f"(d[2]), "+f"(d[3])
        : "r"(a[0]), "r"(a[1]), "r"(a[2]), "r"(a[3]), "r"(b0), "r"(b1));
}
__device__ __forceinline__ void mma_f16(float* d, const uint32_t* a, uint32_t b0, uint32_t b1) {
    asm volatile("mma.sync.aligned.m16n8k16.row.col.f32.f16.f16.f32 "
        "{%0,%1,%2,%3},{%4,%5,%6,%7},{%8,%9},{%0,%1,%2,%3};"
        : "+f"(d[0]), "+f"(d[1]), "+f"(d[2]), "+f"(d[3])
        : "r"(a[0]), "r"(a[1]), "r"(a[2]), "r"(a[3]), "r"(b0), "r"(b1));
}
__device__ __forceinline__ uint32_t pack2(bf16 a, bf16 b) {
    union { bf16 h[2]; uint32_t u; } t;
    t.h[0] = a; t.h[1] = b;
    return t.u;
}
__device__ __forceinline__ uint32_t pack2h(hf a, hf b) {
    union { hf h[2]; uint32_t u; } t;
    t.h[0] = a; t.h[1] = b;
    return t.u;
}
__device__ __forceinline__ void cp16(uint32_t s, const void* g) {
    asm volatile("cp.async.cg.shared.global [%0], [%1], 16;" :: "r"(s), "l"(g));
}
#define CP_COMMIT() asm volatile("cp.async.commit_group;" ::: "memory")
#define CP_WAIT2()  asm volatile("cp.async.wait_group 2;" ::: "memory")

// ---------------- weight conversion (fp32 -> fp16 single) ----------------
__global__ __launch_bounds__(256) void cvt_h(const float* __restrict__ in,
                                             hf* __restrict__ out, int n4)
{
    int i = blockIdx.x * blockDim.x + threadIdx.x;
    if (i >= n4) return;
    float4 v = ((const float4*)in)[i];
    union { hf h[4]; uint2 u; } p;
    p.h[0] = __float2half_rn(v.x);
    p.h[1] = __float2half_rn(v.y);
    p.h[2] = __float2half_rn(v.z);
    p.h[3] = __float2half_rn(v.w);
    ((uint2*)out)[i] = p.u;
}

// ---------------- LayerNorm -> fp16 hi/lo ----------------
__global__ __launch_bounds__(256) void ln_h(const float* __restrict__ x,
                                            const float* __restrict__ gamma,
                                            const float* __restrict__ beta,
                                            hf* __restrict__ yh, hf* __restrict__ yl)
{
    const int row = blockIdx.x;
    const int t = threadIdx.x;
    const float* xr = x + (size_t)row * E_;
    float4 xv = *(const float4*)(xr + t * 4);
    float s = xv.x + xv.y + xv.z + xv.w;
    float sq = xv.x*xv.x + xv.y*xv.y + xv.z*xv.z + xv.w*xv.w;
    #pragma unroll
    for (int o = 16; o > 0; o >>= 1) {
        s  += __shfl_down_sync(0xffffffffu, s, o);
        sq += __shfl_down_sync(0xffffffffu, sq, o);
    }
    __shared__ float sa[8], sb[8];
    const int w = t >> 5, lane = t & 31;
    if (lane == 0) { sa[w] = s; sb[w] = sq; }
    __syncthreads();
    float ts = 0.f, tq = 0.f;
    #pragma unroll
    for (int k = 0; k < 8; k++) { ts += sa[k]; tq += sb[k]; }
    const float mean = ts * (1.0f / E_);
    const float var = tq * (1.0f / E_) - mean * mean;
    const float rstd = rsqrtf(var + 1e-5f);
    float4 gv = *(const float4*)(gamma + t * 4);
    float4 bv = *(const float4*)(beta + t * 4);
    float o4[4];
    o4[0] = (xv.x - mean) * rstd * gv.x + bv.x;
    o4[1] = (xv.y - mean) * rstd * gv.y + bv.y;
    o4[2] = (xv.z - mean) * rstd * gv.z + bv.z;
    o4[3] = (xv.w - mean) * rstd * gv.w + bv.w;
    union { hf b[4]; uint2 u; } ph, pl;
    #pragma unroll
    for (int k = 0; k < 4; k++) {
        hf h = __float2half_rn(o4[k]);
        ph.b[k] = h;
        pl.b[k] = __float2half_rn(o4[k] - __half2float(h));
    }
    const size_t off = (size_t)row * E_ + t * 4;
    *(uint2*)(yh + off) = ph.u;
    *(uint2*)(yl + off) = pl.u;
}

// ---------------- fp16 2-term GEMM, cp.async 4-stage ----------------
// C[M,N] = (Ah+Al)[M,K] @ B[N,K]^T ; Ah/Al fp16 (22-bit), B fp16 single.
#define GK 32
#define RS 40
#define MAT_SZ (128 * RS * 2)       // 10240 B
#define STAGE_SZ (3 * MAT_SZ)       // 30720 B
#define NSTG 4
#define BIAS_OFF (NSTG * STAGE_SZ)  // 122880
#define GSMEM (BIAS_OFF + 512)

// SPLIT: 0 = fp32 C, 1 = bf16 hi/lo, 2 = fp16 hi/lo
template <int RELU, int RES, int SPLIT>
__global__ __launch_bounds__(256, 1)
void gemm_h(const hf* __restrict__ Ah, const hf* __restrict__ Al,
            const hf* __restrict__ Bm,
            const float* __restrict__ bias, const float* __restrict__ res,
            float* __restrict__ C, void* __restrict__ Chi, void* __restrict__ Clo,
            int M, int N, int K)
{
    extern __shared__ char smem[];
    const int tid = threadIdx.x;
    const int lane = tid & 31;
    const int wid = tid >> 5;
    const int wm = wid & 1;
    const int wn = wid >> 1;
    const int bm = blockIdx.y * 128;
    const int bn = blockIdx.x * 128;

    float acc[4][4][4];
    #pragma unroll
    for (int a = 0; a < 4; a++)
        #pragma unroll
        for (int b = 0; b < 4; b++)
            #pragma unroll
            for (int c = 0; c < 4; c++) acc[a][b][c] = 0.f;

    const int prow = tid >> 2;      // 0..63
    const int pc = tid & 3;
    const uint32_t sb0 = smem_u32(smem);
    const int arow = wm * 64 + (lane & 15);
    const int brow = wn * 32 + (lane & 15);
    const int acol = (lane >> 4) * 8;

    if (tid < 128) *(float*)(smem + BIAS_OFF + tid * 4) = bias[bn + tid];

    const int NK = K / GK;

    // stage issue helper (as lambda-free macro-ish inline)
    auto issue_stage = [&](int stage, int ko) {
        const uint32_t sb = sb0 + stage * STAGE_SZ;
        #pragma unroll
        for (int rep = 0; rep < 2; rep++) {
            const int row = prow + rep * 64;
            const uint32_t so = (uint32_t)row * (RS * 2) + pc * 16;
            const size_t ga = (size_t)(bm + row) * K + ko + pc * 8;
            const size_t gb = (size_t)(bn + row) * K + ko + pc * 8;
            cp16(sb + so, Ah + ga);
            cp16(sb + MAT_SZ + so, Al + ga);
            cp16(sb + 2 * MAT_SZ + so, Bm + gb);
        }
    };

    #pragma unroll
    for (int st = 0; st < NSTG - 1; st++) {
        issue_stage(st, st * GK);
        CP_COMMIT();
    }

    for (int kt = 0; kt < NK; kt++) {
        const int buf = kt & 3;
        CP_WAIT2();
        __syncthreads();

        const uint32_t base = sb0 + buf * STAGE_SZ;
        #pragma unroll
        for (int k0 = 0; k0 < 2; k0++) {
            uint32_t ah[4][4], al[4][4];
            #pragma unroll
            for (int mi = 0; mi < 4; mi++) {
                const uint32_t ad = base + (uint32_t)(arow + mi * 16) * (RS * 2) + (k0 * 16 + acol) * 2;
                ldsm_x4(ah[mi], ad);
                ldsm_x4(al[mi], ad + MAT_SZ);
            }
            uint32_t bq[2][4];
            #pragma unroll
            for (int nb = 0; nb < 2; nb++) {
                const uint32_t bd = base + 2 * MAT_SZ + (uint32_t)(brow + nb * 16) * (RS * 2) + (k0 * 16 + acol) * 2;
                ldsm_x4(bq[nb], bd);
            }
            #pragma unroll
            for (int mi = 0; mi < 4; mi++) {
                #pragma unroll
                for (int nb = 0; nb < 2; nb++) {
                    mma_f16(acc[mi][nb*2],   ah[mi], bq[nb][0], bq[nb][2]);
                    mma_f16(acc[mi][nb*2+1], ah[mi], bq[nb][1], bq[nb][3]);
                    mma_f16(acc[mi][nb*2],   al[mi], bq[nb][0], bq[nb][2]);
                    mma_f16(acc[mi][nb*2+1], al[mi], bq[nb][1], bq[nb][3]);
                }
            }
        }

        if (kt + NSTG - 1 < NK) issue_stage((kt + NSTG - 1) & 3, (kt + NSTG - 1) * GK);
        CP_COMMIT();
    }

    // ---------------- epilogue ----------------
    float bv[4][2];
    #pragma unroll
    for (int ni = 0; ni < 4; ni++) {
        const int c0 = wn * 32 + ni * 8 + (lane & 3) * 2;
        bv[ni][0] = *(const float*)(smem + BIAS_OFF + c0 * 4);
        bv[ni][1] = *(const float*)(smem + BIAS_OFF + (c0 + 1) * 4);
    }
    #pragma unroll
    for (int mi = 0; mi < 4; mi++) {
        const int r0 = bm + wm * 64 + mi * 16 + (lane >> 2);
        #pragma unroll
        for (int ni = 0; ni < 4; ni++) {
            const int c0 = bn + wn * 32 + ni * 8 + (lane & 3) * 2;
            #pragma unroll
            for (int h = 0; h < 2; h++) {
                const int r = r0 + h * 8;
                float v0 = acc[mi][ni][h*2]   + bv[ni][0];
                float v1 = acc[mi][ni][h*2+1] + bv[ni][1];
                if (RELU) { v0 = fmaxf(v0, 0.f); v1 = fmaxf(v1, 0.f); }
                const size_t off = (size_t)r * N + c0;
                if (RES) {
                    float2 rr = *(const float2*)(res + off);
                    v0 += rr.x; v1 += rr.y;
                }
                if (SPLIT == 1) {
                    bf16 h0 = __float2bfloat16(v0);
                    bf16 h1 = __float2bfloat16(v1);
                    *(uint32_t*)((bf16*)Chi + off) = pack2(h0, h1);
                    *(uint32_t*)((bf16*)Clo + off) = pack2(__float2bfloat16(v0 - __bfloat162float(h0)),
                                                           __float2bfloat16(v1 - __bfloat162float(h1)));
                } else if (SPLIT == 2) {
                    hf h0 = __float2half_rn(v0);
                    hf h1 = __float2half_rn(v1);
                    *(uint32_t*)((hf*)Chi + off) = pack2h(h0, h1);
                    *(uint32_t*)((hf*)Clo + off) = pack2h(__float2half_rn(v0 - __half2float(h0)),
                                                          __float2half_rn(v1 - __half2float(h1)));
                } else {
                    *(float2*)(C + off) = make_float2(v0, v1);
                }
            }
        }
    }
}

// ---------------- HMMA flash attention (bf16x3 inside, fp16 hi/lo out) ----------------
#define ARS 72
#define ATILE (64 * ARS * 2)
#define A_QH 0
#define A_QL (ATILE)
#define A_KH (2*ATILE)
#define A_KL (3*ATILE)
#define A_VH (4*ATILE)
#define A_VL (5*ATILE)
#define A_BIAS (6*ATILE)
#define ASMEM (6*ATILE + 512)

__global__ __launch_bounds__(128)
void attn_mma(const bf16* __restrict__ qkvh, const bf16* __restrict__ qkvl,
              const float* __restrict__ rel_pos,
              hf* __restrict__ outh, hf* __restrict__ outl)
{
    extern __shared__ char smem[];
    const uint32_t sb = smem_u32(smem);
    const int tid = threadIdx.x;
    const int lane = tid & 31;
    const int w = tid >> 5;
    const int q0 = blockIdx.x * 64;
    const int h = blockIdx.y;
    const int b = blockIdx.z;

    const int rl = lane >> 2;
    const int cl = (lane & 3) * 2;

    {
        const __nv_bfloat162 sc = __floats2bfloat162_rn(0.125f, 0.125f);
        #pragma unroll
        for (int p = 0; p < 4; p++) {
            const int chunk = tid + p * 128;
            const int row = chunk >> 3;
            const int c16 = chunk & 7;
            const size_t ga = (size_t)(b * S_ + q0 + row) * (3 * E_) + h * 64 + c16 * 8;
            uint4 vh = *(const uint4*)(qkvh + ga);
            uint4 vl = *(const uint4*)(qkvl + ga);
            __nv_bfloat162* ph = (__nv_bfloat162*)&vh;
            __nv_bfloat162* pl = (__nv_bfloat162*)&vl;
            #pragma unroll
            for (int k = 0; k < 4; k++) { ph[k] = __hmul2(ph[k], sc); pl[k] = __hmul2(pl[k], sc); }
            const uint32_t so = row * (ARS * 2) + c16 * 16;
            *(uint4*)(smem + A_QH + so) = vh;
            *(uint4*)(smem + A_QL + so) = vl;
        }
    }

    float o[8][4];
    #pragma unroll
    for (int t = 0; t < 8; t++)
        #pragma unroll
        for (int e = 0; e < 4; e++) o[t][e] = 0.f;
    float m0 = -1e30f, m1 = -1e30f, l0 = 0.f, l1 = 0.f;

    const float* rp = rel_pos + (size_t)h * ML_;

    for (int k0 = 0; k0 <= q0; k0 += 64) {
        __syncthreads();
        #pragma unroll
        for (int p = 0; p < 4; p++) {
            const int chunk = tid + p * 128;
            const int row = chunk >> 3;
            const int c16 = chunk & 7;
            const size_t gk = (size_t)(b * S_ + k0 + row) * (3 * E_) + E_ + h * 64 + c16 * 8;
            const size_t gv = gk + E_;
            const uint32_t so = row * (ARS * 2) + c16 * 16;
            *(uint4*)(smem + A_KH + so) = *(const uint4*)(qkvh + gk);
            *(uint4*)(smem + A_KL + so) = *(const uint4*)(qkvl + gk);
            *(uint4*)(smem + A_VH + so) = *(const uint4*)(qkvh + gv);
            *(uint4*)(smem + A_VL + so) = *(const uint4*)(qkvl + gv);
        }
        if (tid < 127) {
            const int idx = q0 - k0 - 63 + tid;
            *(float*)(smem + A_BIAS + tid * 4) = (idx >= 0) ? rp[idx] : 0.f;
        }
        __syncthreads();

        float s[8][4];
        #pragma unroll
        for (int t = 0; t < 8; t++)
            #pragma unroll
            for (int e = 0; e < 4; e++) s[t][e] = 0.f;

        #pragma unroll
        for (int d4 = 0; d4 < 4; d4++) {
            uint32_t ah[4], al[4];
            const uint32_t qa = sb + A_QH + (uint32_t)(w * 16 + (lane & 15)) * (ARS * 2) + (d4 * 16 + (lane >> 4) * 8) * 2;
            ldsm_x4(ah, qa);
            ldsm_x4(al, qa + ATILE);
            #pragma unroll
            for (int nb = 0; nb < 4; nb++) {
                uint32_t kh[4], kl[4];
                const uint32_t ka = sb + A_KH + (uint32_t)(nb * 16 + (lane & 15)) * (ARS * 2) + (d4 * 16 + (lane >> 4) * 8) * 2;
                ldsm_x4(kh, ka);
                ldsm_x4(kl, ka + ATILE);
                mma_bf16(s[nb*2],   ah, kh[0], kh[2]);
                mma_bf16(s[nb*2+1], ah, kh[1], kh[3]);
                mma_bf16(s[nb*2],   ah, kl[0], kl[2]);
                mma_bf16(s[nb*2+1], ah, kl[1], kl[3]);
                mma_bf16(s[nb*2],   al, kh[0], kh[2]);
                mma_bf16(s[nb*2+1], al, kh[1], kh[3]);
            }
        }

        const bool diag = (k0 == q0);
        const int i0 = w * 16 + rl;
        const int i1 = i0 + 8;
        float tmax0 = -1e30f, tmax1 = -1e30f;
        #pragma unroll
        for (int t = 0; t < 8; t++) {
            const int c0 = t * 8 + cl;
            #pragma unroll
            for (int e = 0; e < 4; e++) {
                const int irow = (e < 2) ? i0 : i1;
                const int c = c0 + (e & 1);
                float val = s[t][e] + *(const float*)(smem + A_BIAS + (63 + irow - c) * 4);
                if (diag && c > irow) val = -1e30f;
                s[t][e] = val;
                if (e < 2) tmax0 = fmaxf(tmax0, val);
                else       tmax1 = fmaxf(tmax1, val);
            }
        }
        #pragma unroll
        for (int xo = 1; xo <= 2; xo <<= 1) {
            tmax0 = fmaxf(tmax0, __shfl_xor_sync(0xffffffffu, tmax0, xo));
            tmax1 = fmaxf(tmax1, __shfl_xor_sync(0xffffffffu, tmax1, xo));
        }
        const float mn0 = fmaxf(m0, tmax0);
        const float mn1 = fmaxf(m1, tmax1);
        const float corr0 = __expf(m0 - mn0);
        const float corr1 = __expf(m1 - mn1);
        m0 = mn0; m1 = mn1;

        float rs0 = 0.f, rs1 = 0.f;
        #pragma unroll
        for (int t = 0; t < 8; t++) {
            s[t][0] = __expf(s[t][0] - mn0);
            s[t][1] = __expf(s[t][1] - mn0);
            s[t][2] = __expf(s[t][2] - mn1);
            s[t][3] = __expf(s[t][3] - mn1);
            rs0 += s[t][0] + s[t][1];
            rs1 += s[t][2] + s[t][3];
        }
        #pragma unroll
        for (int xo = 1; xo <= 2; xo <<= 1) {
            rs0 += __shfl_xor_sync(0xffffffffu, rs0, xo);
            rs1 += __shfl_xor_sync(0xffffffffu, rs1, xo);
        }
        l0 = l0 * corr0 + rs0;
        l1 = l1 * corr1 + rs1;
        #pragma unroll
        for (int t = 0; t < 8; t++) {
            o[t][0] *= corr0; o[t][1] *= corr0;
            o[t][2] *= corr1; o[t][3] *= corr1;
        }

        #pragma unroll
        for (int kb = 0; kb < 4; kb++) {
            uint32_t pah[4], pal[4];
            {
                const float* sA = s[2*kb];
                const float* sB = s[2*kb+1];
                bf16 hA0 = __float2bfloat16(sA[0]), hA1 = __float2bfloat16(sA[1]);
                bf16 hA2 = __float2bfloat16(sA[2]), hA3 = __float2bfloat16(sA[3]);
                bf16 hB0 = __float2bfloat16(sB[0]), hB1 = __float2bfloat16(sB[1]);
                bf16 hB2 = __float2bfloat16(sB[2]), hB3 = __float2bfloat16(sB[3]);
                pah[0] = pack2(hA0, hA1);
                pah[1] = pack2(hA2, hA3);
                pah[2] = pack2(hB0, hB1);
                pah[3] = pack2(hB2, hB3);
                pal[0] = pack2(__float2bfloat16(sA[0] - __bfloat162float(hA0)),
                               __float2bfloat16(sA[1] - __bfloat162float(hA1)));
                pal[1] = pack2(__float2bfloat16(sA[2] - __bfloat162float(hA2)),
                               __float2bfloat16(sA[3] - __bfloat162float(hA3)));
                pal[2] = pack2(__float2bfloat16(sB[0] - __bfloat162float(hB0)),
                               __float2bfloat16(sB[1] - __bfloat162float(hB1)));
                pal[3] = pack2(__float2bfloat16(sB[2] - __bfloat162float(hB2)),
                               __float2bfloat16(sB[3] - __bfloat162float(hB3)));
            }
            #pragma unroll
            for (int nb = 0; nb < 4; nb++) {
                uint32_t vh[4], vl[4];
                const uint32_t va = sb + A_VH + (uint32_t)(kb * 16 + (lane & 15)) * (ARS * 2) + (nb * 16 + (lane >> 4) * 8) * 2;
                ldsm_x4_t(vh, va);
                ldsm_x4_t(vl, va + ATILE);
                mma_bf16(o[nb*2],   pah, vh[0], vh[1]);
                mma_bf16(o[nb*2+1], pah, vh[2], vh[3]);
                mma_bf16(o[nb*2],   pah, vl[0], vl[1]);
                mma_bf16(o[nb*2+1], pah, vl[2], vl[3]);
                mma_bf16(o[nb*2],   pal, vh[0], vh[1]);
                mma_bf16(o[nb*2+1], pal, vh[2], vh[3]);
            }
        }
    }

    const float inv0 = 1.0f / l0;
    const float inv1 = 1.0f / l1;
    const int tok0 = b * S_ + q0 + w * 16 + rl;
    const int tok1 = tok0 + 8;
    #pragma unroll
    for (int t = 0; t < 8; t++) {
        const int col = h * 64 + t * 8 + cl;
        float v0 = o[t][0] * inv0, v1 = o[t][1] * inv0;
        float v2 = o[t][2] * inv1, v3 = o[t][3] * inv1;
        hf h0 = __float2half_rn(v0), h1 = __float2half_rn(v1);
        hf h2 = __float2half_rn(v2), h3 = __float2half_rn(v3);
        const size_t o0 = (size_t)tok0 * E_ + col;
        const size_t o1 = (size_t)tok1 * E_ + col;
        *(uint32_t*)(outh + o0) = pack2h(h0, h1);
        *(uint32_t*)(outl + o0) = pack2h(__float2half_rn(v0 - __half2float(h0)),
                                         __float2half_rn(v1 - __half2float(h1)));
        *(uint32_t*)(outh + o1) = pack2h(h2, h3);
        *(uint32_t*)(outl + o1) = pack2h(__float2half_rn(v2 - __half2float(h2)),
                                         __float2half_rn(v3 - __half2float(h3)));
    }
}

// ---------------- launch ----------------
extern "C" void kernel_launch(void* const* d_in, const int* in_sizes, int n_in,
                              void* d_out, int out_size)
{
    const float* x         = (const float*)d_in[0];
    const float* rel_pos   = (const float*)d_in[1];
    const float* in_proj_w = (const float*)d_in[2];
    const float* in_proj_b = (const float*)d_in[3];
    const float* out_w     = (const float*)d_in[4];
    const float* out_b     = (const float*)d_in[5];
    const float* w1        = (const float*)d_in[6];
    const float* b1        = (const float*)d_in[7];
    const float* w2        = (const float*)d_in[8];
    const float* b2        = (const float*)d_in[9];
    const float* ln1_g     = (const float*)d_in[10];
    const float* ln1_b     = (const float*)d_in[11];
    const float* ln2_g     = (const float*)d_in[12];
    const float* ln2_b     = (const float*)d_in[13];
    float* out = (float*)d_out;

    hf *wq, *wo, *w1p, *w2p, *xnh, *xnl, *aoh, *aol, *xmh, *xml, *h1h, *h1l;
    bf16 *qkvh, *qkvl;
    float *x1;
    cudaGetSymbolAddress((void**)&wq, g_wq);  cudaGetSymbolAddress((void**)&wo, g_wo);
    cudaGetSymbolAddress((void**)&w1p, g_w1); cudaGetSymbolAddress((void**)&w2p, g_w2);
    cudaGetSymbolAddress((void**)&xnh, g_xnh); cudaGetSymbolAddress((void**)&xnl, g_xnl);
    cudaGetSymbolAddress((void**)&aoh, g_aoh); cudaGetSymbolAddress((void**)&aol, g_aol);
    cudaGetSymbolAddress((void**)&xmh, g_xmh); cudaGetSymbolAddress((void**)&xml, g_xml);
    cudaGetSymbolAddress((void**)&h1h, g_h1h); cudaGetSymbolAddress((void**)&h1l, g_h1l);
    cudaGetSymbolAddress((void**)&qkvh, g_qkvh); cudaGetSymbolAddress((void**)&qkvl, g_qkvl);
    cudaGetSymbolAddress((void**)&x1, g_x1);

    cudaFuncSetAttribute(gemm_h<0,0,1>, cudaFuncAttributeMaxDynamicSharedMemorySize, GSMEM);
    cudaFuncSetAttribute(gemm_h<0,1,0>, cudaFuncAttributeMaxDynamicSharedMemorySize, GSMEM);
    cudaFuncSetAttribute(gemm_h<1,0,2>, cudaFuncAttributeMaxDynamicSharedMemorySize, GSMEM);
    cudaFuncSetAttribute(attn_mma, cudaFuncAttributeMaxDynamicSharedMemorySize, ASMEM);

    // weight conversion to fp16
    cvt_h<<<(3*E_*E_/4 + 255)/256, 256>>>(in_proj_w, wq, 3*E_*E_/4);
    cvt_h<<<(E_*E_/4 + 255)/256, 256>>>(out_w, wo, E_*E_/4);
    cvt_h<<<(4*E_*E_/4 + 255)/256, 256>>>(w1, w1p, 4*E_*E_/4);
    cvt_h<<<(4*E_*E_/4 + 255)/256, 256>>>(w2, w2p, 4*E_*E_/4);

    // 1) LN1 -> xn hi/lo (fp16)
    ln_h<<<MR, 256>>>(x, ln1_g, ln1_b, xnh, xnl);
    // 2) QKV -> bf16 hi/lo
    gemm_h<0,0,1><<<dim3(3*E_/128, MR/128), 256, GSMEM>>>(
        xnh, xnl, wq, in_proj_b, nullptr, nullptr, qkvh, qkvl, MR, 3*E_, E_);
    // 3) attention -> ao hi/lo (fp16)
    attn_mma<<<dim3(S_/64, H_, B_), 128, ASMEM>>>(qkvh, qkvl, rel_pos, aoh, aol);
    // 4) out-proj + residual -> x1 fp32
    gemm_h<0,1,0><<<dim3(E_/128, MR/128), 256, GSMEM>>>(
        aoh, aol, wo, out_b, x, x1, nullptr, nullptr, MR, E_, E_);
    // 5) LN2 -> xm hi/lo (fp16)
    ln_h<<<MR, 256>>>(x1, ln2_g, ln2_b, xmh, xml);
    // 6) MLP up + ReLU -> h1 hi/lo (fp16)
    gemm_h<1,0,2><<<dim3(4*E_/128, MR/128), 256, GSMEM>>>(
        xmh, xml, w1p, b1, nullptr, nullptr, h1h, h1l, MR, 4*E_, E_);
    // 7) MLP down + residual -> out fp32
    gemm_h<0,1,0><<<dim3(E_/128, MR/128), 256, GSMEM>>>(
        h1h, h1l, w2p, b2, x1, out, nullptr, nullptr, MR, E_, 4*E_);
}

// round 6
// speedup vs baseline: 5.2620x; 1.6208x over previous
#include <cuda_runtime.h>
#include <cuda_bf16.h>
#include <cuda_fp16.h>
#include <cstdint>
#include <cstddef>

// Problem constants
#define B_  4
#define S_  1024
#define E_  1024
#define H_  16
#define HD_ 64
#define ML_ 2048
#define MR  4096   // B*S

typedef __nv_bfloat16 bf16;
typedef __half hf;

// ---------------- static scratch ----------------
__device__ hf    g_wq[3*E_*E_];
__device__ hf    g_wo[E_*E_];
__device__ hf    g_w1[4*E_*E_];
__device__ hf    g_w2[4*E_*E_];
__device__ hf    g_xn[MR*E_];
__device__ bf16  g_qkvh[(size_t)MR*3*E_], g_qkvl[(size_t)MR*3*E_];
__device__ hf    g_ao[MR*E_];
__device__ float g_x1 [MR*E_];
__device__ hf    g_xm[MR*E_];
__device__ hf    g_h1[(size_t)MR*4*E_];

// ---------------- helpers ----------------
__device__ __forceinline__ uint32_t smem_u32(const void* p) {
    uint32_t a;
    asm("{ .reg .u64 t; cvta.to.shared.u64 t, %1; cvt.u32.u64 %0, t; }" : "=r"(a) : "l"(p));
    return a;
}
__device__ __forceinline__ void ldsm_x4(uint32_t* r, uint32_t addr) {
    asm volatile("ldmatrix.sync.aligned.m8n8.x4.shared.b16 {%0,%1,%2,%3}, [%4];"
        : "=r"(r[0]), "=r"(r[1]), "=r"(r[2]), "=r"(r[3]) : "r"(addr));
}
__device__ __forceinline__ void ldsm_x4_t(uint32_t* r, uint32_t addr) {
    asm volatile("ldmatrix.sync.aligned.m8n8.x4.trans.shared.b16 {%0,%1,%2,%3}, [%4];"
        : "=r"(r[0]), "=r"(r[1]), "=r"(r[2]), "=r"(r[3]) : "r"(addr));
}
__device__ __forceinline__ void mma_bf16(float* d, const uint32_t* a, uint32_t b0, uint32_t b1) {
    asm volatile("mma.sync.aligned.m16n8k16.row.col.f32.bf16.bf16.f32 "
        "{%0,%1,%2,%3},{%4,%5,%6,%7},{%8,%9},{%0,%1,%2,%3};"
        : "+f"(d[0]), "+f"(d[1]), "+f"(d[2]), "+f"(d[3])
        : "r"(a[0]), "r"(a[1]), "r"(a[2]), "r"(a[3]), "r"(b0), "r"(b1));
}
__device__ __forceinline__ void mma_f16(float* d, const uint32_t* a, uint32_t b0, uint32_t b1) {
    asm volatile("mma.sync.aligned.m16n8k16.row.col.f32.f16.f16.f32 "
        "{%0,%1,%2,%3},{%4,%5,%6,%7},{%8,%9},{%0,%1,%2,%3};"
        : "+f"(d[0]), "+f"(d[1]), "+f"(d[2]), "+f"(d[3])
        : "r"(a[0]), "r"(a[1]), "r"(a[2]), "r"(a[3]), "r"(b0), "r"(b1));
}
__device__ __forceinline__ uint32_t pack2(bf16 a, bf16 b) {
    union { bf16 h[2]; uint32_t u; } t;
    t.h[0] = a; t.h[1] = b;
    return t.u;
}
__device__ __forceinline__ uint32_t pack2h(hf a, hf b) {
    union { hf h[2]; uint32_t u; } t;
    t.h[0] = a; t.h[1] = b;
    return t.u;
}
__device__ __forceinline__ void cp16(uint32_t s, const void* g) {
    asm volatile("cp.async.cg.shared.global [%0], [%1], 16;" :: "r"(s), "l"(g));
}
#define CP_COMMIT() asm volatile("cp.async.commit_group;" ::: "memory")
#define CP_WAIT2()  asm volatile("cp.async.wait_group 2;" ::: "memory")

// ---------------- weight conversion (fp32 -> fp16 single) ----------------
__global__ __launch_bounds__(256) void cvt_h(const float* __restrict__ in,
                                             hf* __restrict__ out, int n4)
{
    int i = blockIdx.x * blockDim.x + threadIdx.x;
    if (i >= n4) return;
    float4 v = ((const float4*)in)[i];
    union { hf h[4]; uint2 u; } p;
    p.h[0] = __float2half_rn(v.x);
    p.h[1] = __float2half_rn(v.y);
    p.h[2] = __float2half_rn(v.z);
    p.h[3] = __float2half_rn(v.w);
    ((uint2*)out)[i] = p.u;
}

// ---------------- LayerNorm -> fp16 ----------------
__global__ __launch_bounds__(256) void ln_h(const float* __restrict__ x,
                                            const float* __restrict__ gamma,
                                            const float* __restrict__ beta,
                                            hf* __restrict__ y)
{
    const int row = blockIdx.x;
    const int t = threadIdx.x;
    const float* xr = x + (size_t)row * E_;
    float4 xv = *(const float4*)(xr + t * 4);
    float s = xv.x + xv.y + xv.z + xv.w;
    float sq = xv.x*xv.x + xv.y*xv.y + xv.z*xv.z + xv.w*xv.w;
    #pragma unroll
    for (int o = 16; o > 0; o >>= 1) {
        s  += __shfl_down_sync(0xffffffffu, s, o);
        sq += __shfl_down_sync(0xffffffffu, sq, o);
    }
    __shared__ float sa[8], sb[8];
    const int w = t >> 5, lane = t & 31;
    if (lane == 0) { sa[w] = s; sb[w] = sq; }
    __syncthreads();
    float ts = 0.f, tq = 0.f;
    #pragma unroll
    for (int k = 0; k < 8; k++) { ts += sa[k]; tq += sb[k]; }
    const float mean = ts * (1.0f / E_);
    const float var = tq * (1.0f / E_) - mean * mean;
    const float rstd = rsqrtf(var + 1e-5f);
    float4 gv = *(const float4*)(gamma + t * 4);
    float4 bv = *(const float4*)(beta + t * 4);
    union { hf b[4]; uint2 u; } p;
    p.b[0] = __float2half_rn((xv.x - mean) * rstd * gv.x + bv.x);
    p.b[1] = __float2half_rn((xv.y - mean) * rstd * gv.y + bv.y);
    p.b[2] = __float2half_rn((xv.z - mean) * rstd * gv.z + bv.z);
    p.b[3] = __float2half_rn((xv.w - mean) * rstd * gv.w + bv.w);
    *(uint2*)(y + (size_t)row * E_ + t * 4) = p.u;
}

// ---------------- single-term fp16 GEMM, cp.async 4-stage ----------------
// C[M,N] = A[M,K] @ B[N,K]^T ; A,B fp16.
#define GK 32
#define RS 40
#define MAT_SZ (128 * RS * 2)       // 10240 B
#define STAGE_SZ (2 * MAT_SZ)       // 20480 B
#define NSTG 4
#define BIAS_OFF (NSTG * STAGE_SZ)  // 81920
#define GSMEM (BIAS_OFF + 512)

// OUT: 0 = fp32 C, 1 = bf16 hi/lo, 2 = fp16 single
template <int RELU, int RES, int OUT>
__global__ __launch_bounds__(256, 1)
void gemm_1t(const hf* __restrict__ A, const hf* __restrict__ Bm,
             const float* __restrict__ bias, const float* __restrict__ res,
             float* __restrict__ C, void* __restrict__ Chi, void* __restrict__ Clo,
             int M, int N, int K)
{
    extern __shared__ char smem[];
    const int tid = threadIdx.x;
    const int lane = tid & 31;
    const int wid = tid >> 5;
    const int wm = wid & 1;
    const int wn = wid >> 1;
    const int bm = blockIdx.y * 128;
    const int bn = blockIdx.x * 128;

    float acc[4][4][4];
    #pragma unroll
    for (int a = 0; a < 4; a++)
        #pragma unroll
        for (int b = 0; b < 4; b++)
            #pragma unroll
            for (int c = 0; c < 4; c++) acc[a][b][c] = 0.f;

    const int prow = tid >> 2;      // 0..63
    const int pc = tid & 3;
    const uint32_t sb0 = smem_u32(smem);
    const int arow = wm * 64 + (lane & 15);
    const int brow = wn * 32 + (lane & 15);
    const int acol = (lane >> 4) * 8;

    if (tid < 128) *(float*)(smem + BIAS_OFF + tid * 4) = bias[bn + tid];

    const int NK = K / GK;

    auto issue_stage = [&](int stage, int ko) {
        const uint32_t sb = sb0 + stage * STAGE_SZ;
        #pragma unroll
        for (int rep = 0; rep < 2; rep++) {
            const int row = prow + rep * 64;
            const uint32_t so = (uint32_t)row * (RS * 2) + pc * 16;
            const size_t ga = (size_t)(bm + row) * K + ko + pc * 8;
            const size_t gb = (size_t)(bn + row) * K + ko + pc * 8;
            cp16(sb + so, A + ga);
            cp16(sb + MAT_SZ + so, Bm + gb);
        }
    };

    #pragma unroll
    for (int st = 0; st < NSTG - 1; st++) {
        issue_stage(st, st * GK);
        CP_COMMIT();
    }

    for (int kt = 0; kt < NK; kt++) {
        const int buf = kt & 3;
        CP_WAIT2();
        __syncthreads();

        const uint32_t base = sb0 + buf * STAGE_SZ;
        #pragma unroll
        for (int k0 = 0; k0 < 2; k0++) {
            uint32_t ah[4][4];
            #pragma unroll
            for (int mi = 0; mi < 4; mi++) {
                const uint32_t ad = base + (uint32_t)(arow + mi * 16) * (RS * 2) + (k0 * 16 + acol) * 2;
                ldsm_x4(ah[mi], ad);
            }
            uint32_t bq[2][4];
            #pragma unroll
            for (int nb = 0; nb < 2; nb++) {
                const uint32_t bd = base + MAT_SZ + (uint32_t)(brow + nb * 16) * (RS * 2) + (k0 * 16 + acol) * 2;
                ldsm_x4(bq[nb], bd);
            }
            #pragma unroll
            for (int mi = 0; mi < 4; mi++) {
                #pragma unroll
                for (int nb = 0; nb < 2; nb++) {
                    mma_f16(acc[mi][nb*2],   ah[mi], bq[nb][0], bq[nb][2]);
                    mma_f16(acc[mi][nb*2+1], ah[mi], bq[nb][1], bq[nb][3]);
                }
            }
        }

        if (kt + NSTG - 1 < NK) issue_stage((kt + NSTG - 1) & 3, (kt + NSTG - 1) * GK);
        CP_COMMIT();
    }

    // ---------------- epilogue ----------------
    float bv[4][2];
    #pragma unroll
    for (int ni = 0; ni < 4; ni++) {
        const int c0 = wn * 32 + ni * 8 + (lane & 3) * 2;
        bv[ni][0] = *(const float*)(smem + BIAS_OFF + c0 * 4);
        bv[ni][1] = *(const float*)(smem + BIAS_OFF + (c0 + 1) * 4);
    }
    #pragma unroll
    for (int mi = 0; mi < 4; mi++) {
        const int r0 = bm + wm * 64 + mi * 16 + (lane >> 2);
        #pragma unroll
        for (int ni = 0; ni < 4; ni++) {
            const int c0 = bn + wn * 32 + ni * 8 + (lane & 3) * 2;
            #pragma unroll
            for (int h = 0; h < 2; h++) {
                const int r = r0 + h * 8;
                float v0 = acc[mi][ni][h*2]   + bv[ni][0];
                float v1 = acc[mi][ni][h*2+1] + bv[ni][1];
                if (RELU) { v0 = fmaxf(v0, 0.f); v1 = fmaxf(v1, 0.f); }
                const size_t off = (size_t)r * N + c0;
                if (RES) {
                    float2 rr = *(const float2*)(res + off);
                    v0 += rr.x; v1 += rr.y;
                }
                if (OUT == 1) {
                    bf16 h0 = __float2bfloat16(v0);
                    bf16 h1 = __float2bfloat16(v1);
                    *(uint32_t*)((bf16*)Chi + off) = pack2(h0, h1);
                    *(uint32_t*)((bf16*)Clo + off) = pack2(__float2bfloat16(v0 - __bfloat162float(h0)),
                                                           __float2bfloat16(v1 - __bfloat162float(h1)));
                } else if (OUT == 2) {
                    *(uint32_t*)((hf*)Chi + off) = pack2h(__float2half_rn(v0), __float2half_rn(v1));
                } else {
                    *(float2*)(C + off) = make_float2(v0, v1);
                }
            }
        }
    }
}

// ---------------- HMMA flash attention (bf16x3 inside, fp16 out) ----------------
#define ARS 72
#define ATILE (64 * ARS * 2)
#define A_QH 0
#define A_QL (ATILE)
#define A_KH (2*ATILE)
#define A_KL (3*ATILE)
#define A_VH (4*ATILE)
#define A_VL (5*ATILE)
#define A_BIAS (6*ATILE)
#define ASMEM (6*ATILE + 512)

__global__ __launch_bounds__(128)
void attn_mma(const bf16* __restrict__ qkvh, const bf16* __restrict__ qkvl,
              const float* __restrict__ rel_pos,
              hf* __restrict__ outp)
{
    extern __shared__ char smem[];
    const uint32_t sb = smem_u32(smem);
    const int tid = threadIdx.x;
    const int lane = tid & 31;
    const int w = tid >> 5;
    const int q0 = blockIdx.x * 64;
    const int h = blockIdx.y;
    const int b = blockIdx.z;

    const int rl = lane >> 2;
    const int cl = (lane & 3) * 2;

    {
        const __nv_bfloat162 sc = __floats2bfloat162_rn(0.125f, 0.125f);
        #pragma unroll
        for (int p = 0; p < 4; p++) {
            const int chunk = tid + p * 128;
            const int row = chunk >> 3;
            const int c16 = chunk & 7;
            const size_t ga = (size_t)(b * S_ + q0 + row) * (3 * E_) + h * 64 + c16 * 8;
            uint4 vh = *(const uint4*)(qkvh + ga);
            uint4 vl = *(const uint4*)(qkvl + ga);
            __nv_bfloat162* ph = (__nv_bfloat162*)&vh;
            __nv_bfloat162* pl = (__nv_bfloat162*)&vl;
            #pragma unroll
            for (int k = 0; k < 4; k++) { ph[k] = __hmul2(ph[k], sc); pl[k] = __hmul2(pl[k], sc); }
            const uint32_t so = row * (ARS * 2) + c16 * 16;
            *(uint4*)(smem + A_QH + so) = vh;
            *(uint4*)(smem + A_QL + so) = vl;
        }
    }

    float o[8][4];
    #pragma unroll
    for (int t = 0; t < 8; t++)
        #pragma unroll
        for (int e = 0; e < 4; e++) o[t][e] = 0.f;
    float m0 = -1e30f, m1 = -1e30f, l0 = 0.f, l1 = 0.f;

    const float* rp = rel_pos + (size_t)h * ML_;

    for (int k0 = 0; k0 <= q0; k0 += 64) {
        __syncthreads();
        #pragma unroll
        for (int p = 0; p < 4; p++) {
            const int chunk = tid + p * 128;
            const int row = chunk >> 3;
            const int c16 = chunk & 7;
            const size_t gk = (size_t)(b * S_ + k0 + row) * (3 * E_) + E_ + h * 64 + c16 * 8;
            const size_t gv = gk + E_;
            const uint32_t so = row * (ARS * 2) + c16 * 16;
            *(uint4*)(smem + A_KH + so) = *(const uint4*)(qkvh + gk);
            *(uint4*)(smem + A_KL + so) = *(const uint4*)(qkvl + gk);
            *(uint4*)(smem + A_VH + so) = *(const uint4*)(qkvh + gv);
            *(uint4*)(smem + A_VL + so) = *(const uint4*)(qkvl + gv);
        }
        if (tid < 127) {
            const int idx = q0 - k0 - 63 + tid;
            *(float*)(smem + A_BIAS + tid * 4) = (idx >= 0) ? rp[idx] : 0.f;
        }
        __syncthreads();

        float s[8][4];
        #pragma unroll
        for (int t = 0; t < 8; t++)
            #pragma unroll
            for (int e = 0; e < 4; e++) s[t][e] = 0.f;

        #pragma unroll
        for (int d4 = 0; d4 < 4; d4++) {
            uint32_t ah[4], al[4];
            const uint32_t qa = sb + A_QH + (uint32_t)(w * 16 + (lane & 15)) * (ARS * 2) + (d4 * 16 + (lane >> 4) * 8) * 2;
            ldsm_x4(ah, qa);
            ldsm_x4(al, qa + ATILE);
            #pragma unroll
            for (int nb = 0; nb < 4; nb++) {
                uint32_t kh[4], kl[4];
                const uint32_t ka = sb + A_KH + (uint32_t)(nb * 16 + (lane & 15)) * (ARS * 2) + (d4 * 16 + (lane >> 4) * 8) * 2;
                ldsm_x4(kh, ka);
                ldsm_x4(kl, ka + ATILE);
                mma_bf16(s[nb*2],   ah, kh[0], kh[2]);
                mma_bf16(s[nb*2+1], ah, kh[1], kh[3]);
                mma_bf16(s[nb*2],   ah, kl[0], kl[2]);
                mma_bf16(s[nb*2+1], ah, kl[1], kl[3]);
                mma_bf16(s[nb*2],   al, kh[0], kh[2]);
                mma_bf16(s[nb*2+1], al, kh[1], kh[3]);
            }
        }

        const bool diag = (k0 == q0);
        const int i0 = w * 16 + rl;
        const int i1 = i0 + 8;
        float tmax0 = -1e30f, tmax1 = -1e30f;
        #pragma unroll
        for (int t = 0; t < 8; t++) {
            const int c0 = t * 8 + cl;
            #pragma unroll
            for (int e = 0; e < 4; e++) {
                const int irow = (e < 2) ? i0 : i1;
                const int c = c0 + (e & 1);
                float val = s[t][e] + *(const float*)(smem + A_BIAS + (63 + irow - c) * 4);
                if (diag && c > irow) val = -1e30f;
                s[t][e] = val;
                if (e < 2) tmax0 = fmaxf(tmax0, val);
                else       tmax1 = fmaxf(tmax1, val);
            }
        }
        #pragma unroll
        for (int xo = 1; xo <= 2; xo <<= 1) {
            tmax0 = fmaxf(tmax0, __shfl_xor_sync(0xffffffffu, tmax0, xo));
            tmax1 = fmaxf(tmax1, __shfl_xor_sync(0xffffffffu, tmax1, xo));
        }
        const float mn0 = fmaxf(m0, tmax0);
        const float mn1 = fmaxf(m1, tmax1);
        const float corr0 = __expf(m0 - mn0);
        const float corr1 = __expf(m1 - mn1);
        m0 = mn0; m1 = mn1;

        float rs0 = 0.f, rs1 = 0.f;
        #pragma unroll
        for (int t = 0; t < 8; t++) {
            s[t][0] = __expf(s[t][0] - mn0);
            s[t][1] = __expf(s[t][1] - mn0);
            s[t][2] = __expf(s[t][2] - mn1);
            s[t][3] = __expf(s[t][3] - mn1);
            rs0 += s[t][0] + s[t][1];
            rs1 += s[t][2] + s[t][3];
        }
        #pragma unroll
        for (int xo = 1; xo <= 2; xo <<= 1) {
            rs0 += __shfl_xor_sync(0xffffffffu, rs0, xo);
            rs1 += __shfl_xor_sync(0xffffffffu, rs1, xo);
        }
        l0 = l0 * corr0 + rs0;
        l1 = l1 * corr1 + rs1;
        #pragma unroll
        for (int t = 0; t < 8; t++) {
            o[t][0] *= corr0; o[t][1] *= corr0;
            o[t][2] *= corr1; o[t][3] *= corr1;
        }

        #pragma unroll
        for (int kb = 0; kb < 4; kb++) {
            uint32_t pah[4], pal[4];
            {
                const float* sA = s[2*kb];
                const float* sB = s[2*kb+1];
                bf16 hA0 = __float2bfloat16(sA[0]), hA1 = __float2bfloat16(sA[1]);
                bf16 hA2 = __float2bfloat16(sA[2]), hA3 = __float2bfloat16(sA[3]);
                bf16 hB0 = __float2bfloat16(sB[0]), hB1 = __float2bfloat16(sB[1]);
                bf16 hB2 = __float2bfloat16(sB[2]), hB3 = __float2bfloat16(sB[3]);
                pah[0] = pack2(hA0, hA1);
                pah[1] = pack2(hA2, hA3);
                pah[2] = pack2(hB0, hB1);
                pah[3] = pack2(hB2, hB3);
                pal[0] = pack2(__float2bfloat16(sA[0] - __bfloat162float(hA0)),
                               __float2bfloat16(sA[1] - __bfloat162float(hA1)));
                pal[1] = pack2(__float2bfloat16(sA[2] - __bfloat162float(hA2)),
                               __float2bfloat16(sA[3] - __bfloat162float(hA3)));
                pal[2] = pack2(__float2bfloat16(sB[0] - __bfloat162float(hB0)),
                               __float2bfloat16(sB[1] - __bfloat162float(hB1)));
                pal[3] = pack2(__float2bfloat16(sB[2] - __bfloat162float(hB2)),
                               __float2bfloat16(sB[3] - __bfloat162float(hB3)));
            }
            #pragma unroll
            for (int nb = 0; nb < 4; nb++) {
                uint32_t vh[4], vl[4];
                const uint32_t va = sb + A_VH + (uint32_t)(kb * 16 + (lane & 15)) * (ARS * 2) + (nb * 16 + (lane >> 4) * 8) * 2;
                ldsm_x4_t(vh, va);
                ldsm_x4_t(vl, va + ATILE);
                mma_bf16(o[nb*2],   pah, vh[0], vh[1]);
                mma_bf16(o[nb*2+1], pah, vh[2], vh[3]);
                mma_bf16(o[nb*2],   pah, vl[0], vl[1]);
                mma_bf16(o[nb*2+1], pah, vl[2], vl[3]);
                mma_bf16(o[nb*2],   pal, vh[0], vh[1]);
                mma_bf16(o[nb*2+1], pal, vh[2], vh[3]);
            }
        }
    }

    const float inv0 = 1.0f / l0;
    const float inv1 = 1.0f / l1;
    const int tok0 = b * S_ + q0 + w * 16 + rl;
    const int tok1 = tok0 + 8;
    #pragma unroll
    for (int t = 0; t < 8; t++) {
        const int col = h * 64 + t * 8 + cl;
        const size_t o0 = (size_t)tok0 * E_ + col;
        const size_t o1 = (size_t)tok1 * E_ + col;
        *(uint32_t*)(outp + o0) = pack2h(__float2half_rn(o[t][0] * inv0), __float2half_rn(o[t][1] * inv0));
        *(uint32_t*)(outp + o1) = pack2h(__float2half_rn(o[t][2] * inv1), __float2half_rn(o[t][3] * inv1));
    }
}

// ---------------- launch ----------------
extern "C" void kernel_launch(void* const* d_in, const int* in_sizes, int n_in,
                              void* d_out, int out_size)
{
    const float* x         = (const float*)d_in[0];
    const float* rel_pos   = (const float*)d_in[1];
    const float* in_proj_w = (const float*)d_in[2];
    const float* in_proj_b = (const float*)d_in[3];
    const float* out_w     = (const float*)d_in[4];
    const float* out_b     = (const float*)d_in[5];
    const float* w1        = (const float*)d_in[6];
    const float* b1        = (const float*)d_in[7];
    const float* w2        = (const float*)d_in[8];
    const float* b2        = (const float*)d_in[9];
    const float* ln1_g     = (const float*)d_in[10];
    const float* ln1_b     = (const float*)d_in[11];
    const float* ln2_g     = (const float*)d_in[12];
    const float* ln2_b     = (const float*)d_in[13];
    float* out = (float*)d_out;

    hf *wq, *wo, *w1p, *w2p, *xn, *ao, *xm, *h1;
    bf16 *qkvh, *qkvl;
    float *x1;
    cudaGetSymbolAddress((void**)&wq, g_wq);  cudaGetSymbolAddress((void**)&wo, g_wo);
    cudaGetSymbolAddress((void**)&w1p, g_w1); cudaGetSymbolAddress((void**)&w2p, g_w2);
    cudaGetSymbolAddress((void**)&xn, g_xn);  cudaGetSymbolAddress((void**)&ao, g_ao);
    cudaGetSymbolAddress((void**)&xm, g_xm);  cudaGetSymbolAddress((void**)&h1, g_h1);
    cudaGetSymbolAddress((void**)&qkvh, g_qkvh); cudaGetSymbolAddress((void**)&qkvl, g_qkvl);
    cudaGetSymbolAddress((void**)&x1, g_x1);

    cudaFuncSetAttribute(gemm_1t<0,0,1>, cudaFuncAttributeMaxDynamicSharedMemorySize, GSMEM);
    cudaFuncSetAttribute(gemm_1t<0,1,0>, cudaFuncAttributeMaxDynamicSharedMemorySize, GSMEM);
    cudaFuncSetAttribute(gemm_1t<1,0,2>, cudaFuncAttributeMaxDynamicSharedMemorySize, GSMEM);
    cudaFuncSetAttribute(attn_mma, cudaFuncAttributeMaxDynamicSharedMemorySize, ASMEM);

    // weight conversion to fp16
    cvt_h<<<(3*E_*E_/4 + 255)/256, 256>>>(in_proj_w, wq, 3*E_*E_/4);
    cvt_h<<<(E_*E_/4 + 255)/256, 256>>>(out_w, wo, E_*E_/4);
    cvt_h<<<(4*E_*E_/4 + 255)/256, 256>>>(w1, w1p, 4*E_*E_/4);
    cvt_h<<<(4*E_*E_/4 + 255)/256, 256>>>(w2, w2p, 4*E_*E_/4);

    // 1) LN1 -> xn (fp16)
    ln_h<<<MR, 256>>>(x, ln1_g, ln1_b, xn);
    // 2) QKV -> bf16 hi/lo
    gemm_1t<0,0,1><<<dim3(3*E_/128, MR/128), 256, GSMEM>>>(
        xn, wq, in_proj_b, nullptr, nullptr, qkvh, qkvl, MR, 3*E_, E_);
    // 3) attention -> ao (fp16)
    attn_mma<<<dim3(S_/64, H_, B_), 128, ASMEM>>>(qkvh, qkvl, rel_pos, ao);
    // 4) out-proj + residual -> x1 fp32
    gemm_1t<0,1,0><<<dim3(E_/128, MR/128), 256, GSMEM>>>(
        ao, wo, out_b, x, x1, nullptr, nullptr, MR, E_, E_);
    // 5) LN2 -> xm (fp16)
    ln_h<<<MR, 256>>>(x1, ln2_g, ln2_b, xm);
    // 6) MLP up + ReLU -> h1 (fp16)
    gemm_1t<1,0,2><<<dim3(4*E_/128, MR/128), 256, GSMEM>>>(
        xm, w1p, b1, nullptr, nullptr, h1, nullptr, MR, 4*E_, E_);
    // 7) MLP down + residual -> out fp32
    gemm_1t<0,1,0><<<dim3(E_/128, MR/128), 256, GSMEM>>>(
        h1, w2p, b2, x1, out, nullptr, nullptr, MR, E_, 4*E_);
}

// round 7
// speedup vs baseline: 6.0804x; 1.1555x over previous
#include <cuda_runtime.h>
#include <cuda_bf16.h>
#include <cuda_fp16.h>
#include <cstdint>
#include <cstddef>

// Problem constants
#define B_  4
#define S_  1024
#define E_  1024
#define H_  16
#define HD_ 64
#define ML_ 2048
#define MR  4096   // B*S

typedef __nv_bfloat16 bf16;
typedef __half hf;

// ---------------- static scratch ----------------
__device__ hf    g_wq[3*E_*E_];
__device__ hf    g_wo[E_*E_];
__device__ hf    g_w1[4*E_*E_];
__device__ hf    g_w2[4*E_*E_];
__device__ hf    g_xn[MR*E_];
__device__ hf    g_qkvh[(size_t)MR*3*E_];
__device__ hf    g_qkvl[(size_t)MR*E_];      // lo only for Q third
__device__ hf    g_ao[MR*E_];
__device__ float g_x1 [MR*E_];
__device__ hf    g_xm[MR*E_];
__device__ hf    g_h1[(size_t)MR*4*E_];

// ---------------- helpers ----------------
__device__ __forceinline__ uint32_t smem_u32(const void* p) {
    uint32_t a;
    asm("{ .reg .u64 t; cvta.to.shared.u64 t, %1; cvt.u32.u64 %0, t; }" : "=r"(a) : "l"(p));
    return a;
}
__device__ __forceinline__ void ldsm_x4(uint32_t* r, uint32_t addr) {
    asm volatile("ldmatrix.sync.aligned.m8n8.x4.shared.b16 {%0,%1,%2,%3}, [%4];"
        : "=r"(r[0]), "=r"(r[1]), "=r"(r[2]), "=r"(r[3]) : "r"(addr));
}
__device__ __forceinline__ void ldsm_x4_t(uint32_t* r, uint32_t addr) {
    asm volatile("ldmatrix.sync.aligned.m8n8.x4.trans.shared.b16 {%0,%1,%2,%3}, [%4];"
        : "=r"(r[0]), "=r"(r[1]), "=r"(r[2]), "=r"(r[3]) : "r"(addr));
}
__device__ __forceinline__ void mma_f16(float* d, const uint32_t* a, uint32_t b0, uint32_t b1) {
    asm volatile("mma.sync.aligned.m16n8k16.row.col.f32.f16.f16.f32 "
        "{%0,%1,%2,%3},{%4,%5,%6,%7},{%8,%9},{%0,%1,%2,%3};"
        : "+f"(d[0]), "+f"(d[1]), "+f"(d[2]), "+f"(d[3])
        : "r"(a[0]), "r"(a[1]), "r"(a[2]), "r"(a[3]), "r"(b0), "r"(b1));
}
__device__ __forceinline__ uint32_t pack2h(hf a, hf b) {
    union { hf h[2]; uint32_t u; } t;
    t.h[0] = a; t.h[1] = b;
    return t.u;
}
__device__ __forceinline__ void cp16(uint32_t s, const void* g) {
    asm volatile("cp.async.cg.shared.global [%0], [%1], 16;" :: "r"(s), "l"(g));
}
#define CP_COMMIT() asm volatile("cp.async.commit_group;" ::: "memory")
#define CP_WAIT2()  asm volatile("cp.async.wait_group 2;" ::: "memory")

// ---------------- weight conversion (fp32 -> fp16 single) ----------------
__global__ __launch_bounds__(256) void cvt_h(const float* __restrict__ in,
                                             hf* __restrict__ out, int n4)
{
    int i = blockIdx.x * blockDim.x + threadIdx.x;
    if (i >= n4) return;
    float4 v = ((const float4*)in)[i];
    union { hf h[4]; uint2 u; } p;
    p.h[0] = __float2half_rn(v.x);
    p.h[1] = __float2half_rn(v.y);
    p.h[2] = __float2half_rn(v.z);
    p.h[3] = __float2half_rn(v.w);
    ((uint2*)out)[i] = p.u;
}

// ---------------- LayerNorm -> fp16 ----------------
__global__ __launch_bounds__(256) void ln_h(const float* __restrict__ x,
                                            const float* __restrict__ gamma,
                                            const float* __restrict__ beta,
                                            hf* __restrict__ y)
{
    const int row = blockIdx.x;
    const int t = threadIdx.x;
    const float* xr = x + (size_t)row * E_;
    float4 xv = *(const float4*)(xr + t * 4);
    float s = xv.x + xv.y + xv.z + xv.w;
    float sq = xv.x*xv.x + xv.y*xv.y + xv.z*xv.z + xv.w*xv.w;
    #pragma unroll
    for (int o = 16; o > 0; o >>= 1) {
        s  += __shfl_down_sync(0xffffffffu, s, o);
        sq += __shfl_down_sync(0xffffffffu, sq, o);
    }
    __shared__ float sa[8], sb[8];
    const int w = t >> 5, lane = t & 31;
    if (lane == 0) { sa[w] = s; sb[w] = sq; }
    __syncthreads();
    float ts = 0.f, tq = 0.f;
    #pragma unroll
    for (int k = 0; k < 8; k++) { ts += sa[k]; tq += sb[k]; }
    const float mean = ts * (1.0f / E_);
    const float var = tq * (1.0f / E_) - mean * mean;
    const float rstd = rsqrtf(var + 1e-5f);
    float4 gv = *(const float4*)(gamma + t * 4);
    float4 bv = *(const float4*)(beta + t * 4);
    union { hf b[4]; uint2 u; } p;
    p.b[0] = __float2half_rn((xv.x - mean) * rstd * gv.x + bv.x);
    p.b[1] = __float2half_rn((xv.y - mean) * rstd * gv.y + bv.y);
    p.b[2] = __float2half_rn((xv.z - mean) * rstd * gv.z + bv.z);
    p.b[3] = __float2half_rn((xv.w - mean) * rstd * gv.w + bv.w);
    *(uint2*)(y + (size_t)row * E_ + t * 4) = p.u;
}

// ---------------- single-term fp16 GEMM, cp.async 4-stage ----------------
#define GK 32
#define RS 40
#define MAT_SZ (128 * RS * 2)       // 10240 B
#define STAGE_SZ (2 * MAT_SZ)       // 20480 B
#define NSTG 4
#define BIAS_OFF (NSTG * STAGE_SZ)  // 81920
#define GSMEM (BIAS_OFF + 512)

// OUT: 0 = fp32 C; 2 = fp16 single; 3 = fp16 hi always + lo gated to col<E_ (QKV)
template <int RELU, int RES, int OUT>
__global__ __launch_bounds__(256, 1)
void gemm_1t(const hf* __restrict__ A, const hf* __restrict__ Bm,
             const float* __restrict__ bias, const float* __restrict__ res,
             float* __restrict__ C, hf* __restrict__ Chi, hf* __restrict__ Clo,
             int M, int N, int K)
{
    extern __shared__ char smem[];
    const int tid = threadIdx.x;
    const int lane = tid & 31;
    const int wid = tid >> 5;
    const int wm = wid & 1;
    const int wn = wid >> 1;
    const int bm = blockIdx.y * 128;
    const int bn = blockIdx.x * 128;

    float acc[4][4][4];
    #pragma unroll
    for (int a = 0; a < 4; a++)
        #pragma unroll
        for (int b = 0; b < 4; b++)
            #pragma unroll
            for (int c = 0; c < 4; c++) acc[a][b][c] = 0.f;

    const int prow = tid >> 2;
    const int pc = tid & 3;
    const uint32_t sb0 = smem_u32(smem);
    const int arow = wm * 64 + (lane & 15);
    const int brow = wn * 32 + (lane & 15);
    const int acol = (lane >> 4) * 8;

    if (tid < 128) *(float*)(smem + BIAS_OFF + tid * 4) = bias[bn + tid];

    const int NK = K / GK;

    auto issue_stage = [&](int stage, int ko) {
        const uint32_t sb = sb0 + stage * STAGE_SZ;
        #pragma unroll
        for (int rep = 0; rep < 2; rep++) {
            const int row = prow + rep * 64;
            const uint32_t so = (uint32_t)row * (RS * 2) + pc * 16;
            const size_t ga = (size_t)(bm + row) * K + ko + pc * 8;
            const size_t gb = (size_t)(bn + row) * K + ko + pc * 8;
            cp16(sb + so, A + ga);
            cp16(sb + MAT_SZ + so, Bm + gb);
        }
    };

    #pragma unroll
    for (int st = 0; st < NSTG - 1; st++) {
        issue_stage(st, st * GK);
        CP_COMMIT();
    }

    for (int kt = 0; kt < NK; kt++) {
        const int buf = kt & 3;
        CP_WAIT2();
        __syncthreads();

        const uint32_t base = sb0 + buf * STAGE_SZ;
        #pragma unroll
        for (int k0 = 0; k0 < 2; k0++) {
            uint32_t ah[4][4];
            #pragma unroll
            for (int mi = 0; mi < 4; mi++) {
                const uint32_t ad = base + (uint32_t)(arow + mi * 16) * (RS * 2) + (k0 * 16 + acol) * 2;
                ldsm_x4(ah[mi], ad);
            }
            uint32_t bq[2][4];
            #pragma unroll
            for (int nb = 0; nb < 2; nb++) {
                const uint32_t bd = base + MAT_SZ + (uint32_t)(brow + nb * 16) * (RS * 2) + (k0 * 16 + acol) * 2;
                ldsm_x4(bq[nb], bd);
            }
            #pragma unroll
            for (int mi = 0; mi < 4; mi++) {
                #pragma unroll
                for (int nb = 0; nb < 2; nb++) {
                    mma_f16(acc[mi][nb*2],   ah[mi], bq[nb][0], bq[nb][2]);
                    mma_f16(acc[mi][nb*2+1], ah[mi], bq[nb][1], bq[nb][3]);
                }
            }
        }

        if (kt + NSTG - 1 < NK) issue_stage((kt + NSTG - 1) & 3, (kt + NSTG - 1) * GK);
        CP_COMMIT();
    }

    // ---------------- epilogue ----------------
    float bv[4][2];
    #pragma unroll
    for (int ni = 0; ni < 4; ni++) {
        const int c0 = wn * 32 + ni * 8 + (lane & 3) * 2;
        bv[ni][0] = *(const float*)(smem + BIAS_OFF + c0 * 4);
        bv[ni][1] = *(const float*)(smem + BIAS_OFF + (c0 + 1) * 4);
    }
    #pragma unroll
    for (int mi = 0; mi < 4; mi++) {
        const int r0 = bm + wm * 64 + mi * 16 + (lane >> 2);
        #pragma unroll
        for (int ni = 0; ni < 4; ni++) {
            const int c0 = bn + wn * 32 + ni * 8 + (lane & 3) * 2;
            #pragma unroll
            for (int h = 0; h < 2; h++) {
                const int r = r0 + h * 8;
                float v0 = acc[mi][ni][h*2]   + bv[ni][0];
                float v1 = acc[mi][ni][h*2+1] + bv[ni][1];
                if (RELU) { v0 = fmaxf(v0, 0.f); v1 = fmaxf(v1, 0.f); }
                const size_t off = (size_t)r * N + c0;
                if (RES) {
                    float2 rr = *(const float2*)(res + off);
                    v0 += rr.x; v1 += rr.y;
                }
                if (OUT == 2) {
                    *(uint32_t*)(Chi + off) = pack2h(__float2half_rn(v0), __float2half_rn(v1));
                } else if (OUT == 3) {
                    hf h0 = __float2half_rn(v0);
                    hf h1 = __float2half_rn(v1);
                    *(uint32_t*)(Chi + off) = pack2h(h0, h1);
                    if (c0 < E_) {
                        // Q third: store lo residual at [row][c0] in the E_-wide lo array
                        const size_t loff = (size_t)r * E_ + c0;
                        *(uint32_t*)(Clo + loff) = pack2h(__float2half_rn(v0 - __half2float(h0)),
                                                          __float2half_rn(v1 - __half2float(h1)));
                    }
                } else {
                    *(float2*)(C + off) = make_float2(v0, v1);
                }
            }
        }
    }
}

// ---------------- fp16 flash attention: 2-term QK (Qh+Ql)*K, 1-term PV ----------------
#define ARS 72
#define ATILE (64 * ARS * 2)       // 9216 B
#define A_QH 0
#define A_QL (ATILE)
#define A_KH (2*ATILE)
#define A_VH (3*ATILE)
#define A_BIAS (4*ATILE)
#define ASMEM (4*ATILE + 512)

__global__ __launch_bounds__(128)
void attn_mma(const hf* __restrict__ qkvh, const hf* __restrict__ qkvl,
              const float* __restrict__ rel_pos,
              hf* __restrict__ outp)
{
    extern __shared__ char smem[];
    const uint32_t sb = smem_u32(smem);
    const int tid = threadIdx.x;
    const int lane = tid & 31;
    const int w = tid >> 5;
    const int q0 = blockIdx.x * 64;
    const int h = blockIdx.y;
    const int b = blockIdx.z;

    const int rl = lane >> 2;
    const int cl = (lane & 3) * 2;

    // load Q tile hi/lo, scaled by 0.125 (exact power-of-two scale)
    {
        const __half2 sc = __floats2half2_rn(0.125f, 0.125f);
        #pragma unroll
        for (int p = 0; p < 4; p++) {
            const int chunk = tid + p * 128;
            const int row = chunk >> 3;
            const int c16 = chunk & 7;
            const size_t gh = (size_t)(b * S_ + q0 + row) * (3 * E_) + h * 64 + c16 * 8;
            const size_t gl = (size_t)(b * S_ + q0 + row) * E_ + h * 64 + c16 * 8;
            uint4 vh = *(const uint4*)(qkvh + gh);
            uint4 vl = *(const uint4*)(qkvl + gl);
            __half2* ph = (__half2*)&vh;
            __half2* pl = (__half2*)&vl;
            #pragma unroll
            for (int k = 0; k < 4; k++) { ph[k] = __hmul2(ph[k], sc); pl[k] = __hmul2(pl[k], sc); }
            const uint32_t so = row * (ARS * 2) + c16 * 16;
            *(uint4*)(smem + A_QH + so) = vh;
            *(uint4*)(smem + A_QL + so) = vl;
        }
    }

    float o[8][4];
    #pragma unroll
    for (int t = 0; t < 8; t++)
        #pragma unroll
        for (int e = 0; e < 4; e++) o[t][e] = 0.f;
    float m0 = -1e30f, m1 = -1e30f, l0 = 0.f, l1 = 0.f;

    const float* rp = rel_pos + (size_t)h * ML_;

    for (int k0 = 0; k0 <= q0; k0 += 64) {
        __syncthreads();
        #pragma unroll
        for (int p = 0; p < 2; p++) {
            const int chunk = tid + p * 128;      // 256 chunks cover 64 rows x 4 c16... 
            const int row = chunk >> 2;           // 4 x 16B chunks per... no: 64 rows * 8 c16 = 512
            const int c16x = chunk & 3;
            // K and V each: 512 16B-chunks; use 2 chunks per thread per matrix via two sub-iterations
            #pragma unroll
            for (int half = 0; half < 2; half++) {
                const int rowk = (chunk >> 2);
                const int c16 = c16x * 2 + half;
                const size_t gk = (size_t)(b * S_ + k0 + rowk) * (3 * E_) + E_ + h * 64 + c16 * 8;
                const size_t gv = gk + E_;
                const uint32_t so = rowk * (ARS * 2) + c16 * 16;
                *(uint4*)(smem + A_KH + so) = *(const uint4*)(qkvh + gk);
                *(uint4*)(smem + A_VH + so) = *(const uint4*)(qkvh + gv);
            }
        }
        if (tid < 127) {
            const int idx = q0 - k0 - 63 + tid;
            *(float*)(smem + A_BIAS + tid * 4) = (idx >= 0) ? rp[idx] : 0.f;
        }
        __syncthreads();

        float s[8][4];
        #pragma unroll
        for (int t = 0; t < 8; t++)
            #pragma unroll
            for (int e = 0; e < 4; e++) s[t][e] = 0.f;

        #pragma unroll
        for (int d4 = 0; d4 < 4; d4++) {
            uint32_t qh_[4], ql_[4];
            const uint32_t qa = sb + A_QH + (uint32_t)(w * 16 + (lane & 15)) * (ARS * 2) + (d4 * 16 + (lane >> 4) * 8) * 2;
            ldsm_x4(qh_, qa);
            ldsm_x4(ql_, qa + ATILE);
            #pragma unroll
            for (int nb = 0; nb < 4; nb++) {
                uint32_t kh_[4];
                const uint32_t ka = sb + A_KH + (uint32_t)(nb * 16 + (lane & 15)) * (ARS * 2) + (d4 * 16 + (lane >> 4) * 8) * 2;
                ldsm_x4(kh_, ka);
                mma_f16(s[nb*2],   qh_, kh_[0], kh_[2]);
                mma_f16(s[nb*2+1], qh_, kh_[1], kh_[3]);
                mma_f16(s[nb*2],   ql_, kh_[0], kh_[2]);
                mma_f16(s[nb*2+1], ql_, kh_[1], kh_[3]);
            }
        }

        const bool diag = (k0 == q0);
        const int i0 = w * 16 + rl;
        const int i1 = i0 + 8;
        float tmax0 = -1e30f, tmax1 = -1e30f;
        #pragma unroll
        for (int t = 0; t < 8; t++) {
            const int c0 = t * 8 + cl;
            #pragma unroll
            for (int e = 0; e < 4; e++) {
                const int irow = (e < 2) ? i0 : i1;
                const int c = c0 + (e & 1);
                float val = s[t][e] + *(const float*)(smem + A_BIAS + (63 + irow - c) * 4);
                if (diag && c > irow) val = -1e30f;
                s[t][e] = val;
                if (e < 2) tmax0 = fmaxf(tmax0, val);
                else       tmax1 = fmaxf(tmax1, val);
            }
        }
        #pragma unroll
        for (int xo = 1; xo <= 2; xo <<= 1) {
            tmax0 = fmaxf(tmax0, __shfl_xor_sync(0xffffffffu, tmax0, xo));
            tmax1 = fmaxf(tmax1, __shfl_xor_sync(0xffffffffu, tmax1, xo));
        }
        const float mn0 = fmaxf(m0, tmax0);
        const float mn1 = fmaxf(m1, tmax1);
        const float corr0 = __expf(m0 - mn0);
        const float corr1 = __expf(m1 - mn1);
        m0 = mn0; m1 = mn1;

        float rs0 = 0.f, rs1 = 0.f;
        #pragma unroll
        for (int t = 0; t < 8; t++) {
            s[t][0] = __expf(s[t][0] - mn0);
            s[t][1] = __expf(s[t][1] - mn0);
            s[t][2] = __expf(s[t][2] - mn1);
            s[t][3] = __expf(s[t][3] - mn1);
            rs0 += s[t][0] + s[t][1];
            rs1 += s[t][2] + s[t][3];
        }
        #pragma unroll
        for (int xo = 1; xo <= 2; xo <<= 1) {
            rs0 += __shfl_xor_sync(0xffffffffu, rs0, xo);
            rs1 += __shfl_xor_sync(0xffffffffu, rs1, xo);
        }
        l0 = l0 * corr0 + rs0;
        l1 = l1 * corr1 + rs1;
        #pragma unroll
        for (int t = 0; t < 8; t++) {
            o[t][0] *= corr0; o[t][1] *= corr0;
            o[t][2] *= corr1; o[t][3] *= corr1;
        }

        // PV single-term: P fp16, V fp16
        #pragma unroll
        for (int kb = 0; kb < 4; kb++) {
            uint32_t pa[4];
            {
                const float* sA = s[2*kb];
                const float* sB = s[2*kb+1];
                pa[0] = pack2h(__float2half_rn(sA[0]), __float2half_rn(sA[1]));
                pa[1] = pack2h(__float2half_rn(sA[2]), __float2half_rn(sA[3]));
                pa[2] = pack2h(__float2half_rn(sB[0]), __float2half_rn(sB[1]));
                pa[3] = pack2h(__float2half_rn(sB[2]), __float2half_rn(sB[3]));
            }
            #pragma unroll
            for (int nb = 0; nb < 4; nb++) {
                uint32_t vh_[4];
                const uint32_t va = sb + A_VH + (uint32_t)(kb * 16 + (lane & 15)) * (ARS * 2) + (nb * 16 + (lane >> 4) * 8) * 2;
                ldsm_x4_t(vh_, va);
                mma_f16(o[nb*2],   pa, vh_[0], vh_[1]);
                mma_f16(o[nb*2+1], pa, vh_[2], vh_[3]);
            }
        }
    }

    const float inv0 = 1.0f / l0;
    const float inv1 = 1.0f / l1;
    const int tok0 = b * S_ + q0 + w * 16 + rl;
    const int tok1 = tok0 + 8;
    #pragma unroll
    for (int t = 0; t < 8; t++) {
        const int col = h * 64 + t * 8 + cl;
        const size_t o0 = (size_t)tok0 * E_ + col;
        const size_t o1 = (size_t)tok1 * E_ + col;
        *(uint32_t*)(outp + o0) = pack2h(__float2half_rn(o[t][0] * inv0), __float2half_rn(o[t][1] * inv0));
        *(uint32_t*)(outp + o1) = pack2h(__float2half_rn(o[t][2] * inv1), __float2half_rn(o[t][3] * inv1));
    }
}

// ---------------- launch ----------------
extern "C" void kernel_launch(void* const* d_in, const int* in_sizes, int n_in,
                              void* d_out, int out_size)
{
    const float* x         = (const float*)d_in[0];
    const float* rel_pos   = (const float*)d_in[1];
    const float* in_proj_w = (const float*)d_in[2];
    const float* in_proj_b = (const float*)d_in[3];
    const float* out_w     = (const float*)d_in[4];
    const float* out_b     = (const float*)d_in[5];
    const float* w1        = (const float*)d_in[6];
    const float* b1        = (const float*)d_in[7];
    const float* w2        = (const float*)d_in[8];
    const float* b2        = (const float*)d_in[9];
    const float* ln1_g     = (const float*)d_in[10];
    const float* ln1_b     = (const float*)d_in[11];
    const float* ln2_g     = (const float*)d_in[12];
    const float* ln2_b     = (const float*)d_in[13];
    float* out = (float*)d_out;

    hf *wq, *wo, *w1p, *w2p, *xn, *ao, *xm, *h1, *qkvh, *qkvl;
    float *x1;
    cudaGetSymbolAddress((void**)&wq, g_wq);  cudaGetSymbolAddress((void**)&wo, g_wo);
    cudaGetSymbolAddress((void**)&w1p, g_w1); cudaGetSymbolAddress((void**)&w2p, g_w2);
    cudaGetSymbolAddress((void**)&xn, g_xn);  cudaGetSymbolAddress((void**)&ao, g_ao);
    cudaGetSymbolAddress((void**)&xm, g_xm);  cudaGetSymbolAddress((void**)&h1, g_h1);
    cudaGetSymbolAddress((void**)&qkvh, g_qkvh); cudaGetSymbolAddress((void**)&qkvl, g_qkvl);
    cudaGetSymbolAddress((void**)&x1, g_x1);

    cudaFuncSetAttribute(gemm_1t<0,0,3>, cudaFuncAttributeMaxDynamicSharedMemorySize, GSMEM);
    cudaFuncSetAttribute(gemm_1t<0,1,0>, cudaFuncAttributeMaxDynamicSharedMemorySize, GSMEM);
    cudaFuncSetAttribute(gemm_1t<1,0,2>, cudaFuncAttributeMaxDynamicSharedMemorySize, GSMEM);
    cudaFuncSetAttribute(attn_mma, cudaFuncAttributeMaxDynamicSharedMemorySize, ASMEM);

    // weight conversion to fp16
    cvt_h<<<(3*E_*E_/4 + 255)/256, 256>>>(in_proj_w, wq, 3*E_*E_/4);
    cvt_h<<<(E_*E_/4 + 255)/256, 256>>>(out_w, wo, E_*E_/4);
    cvt_h<<<(4*E_*E_/4 + 255)/256, 256>>>(w1, w1p, 4*E_*E_/4);
    cvt_h<<<(4*E_*E_/4 + 255)/256, 256>>>(w2, w2p, 4*E_*E_/4);

    // 1) LN1 -> xn (fp16)
    ln_h<<<MR, 256>>>(x, ln1_g, ln1_b, xn);
    // 2) QKV -> fp16 hi (+ lo for Q third)
    gemm_1t<0,0,3><<<dim3(3*E_/128, MR/128), 256, GSMEM>>>(
        xn, wq, in_proj_b, nullptr, nullptr, qkvh, qkvl, MR, 3*E_, E_);
    // 3) attention -> ao (fp16)
    attn_mma<<<dim3(S_/64, H_, B_), 128, ASMEM>>>(qkvh, qkvl, rel_pos, ao);
    // 4) out-proj + residual -> x1 fp32
    gemm_1t<0,1,0><<<dim3(E_/128, MR/128), 256, GSMEM>>>(
        ao, wo, out_b, x, x1, nullptr, nullptr, MR, E_, E_);
    // 5) LN2 -> xm (fp16)
    ln_h<<<MR, 256>>>(x1, ln2_g, ln2_b, xm);
    // 6) MLP up + ReLU -> h1 (fp16)
    gemm_1t<1,0,2><<<dim3(4*E_/128, MR/128), 256, GSMEM>>>(
        xm, w1p, b1, nullptr, nullptr, h1, nullptr, MR, 4*E_, E_);
    // 7) MLP down + residual -> out fp32
    gemm_1t<0,1,0><<<dim3(E_/128, MR/128), 256, GSMEM>>>(
        h1, w2p, b2, x1, out, nullptr, nullptr, MR, E_, 4*E_);
}

// round 8
// speedup vs baseline: 6.2582x; 1.0292x over previous
#include <cuda_runtime.h>
#include <cuda_bf16.h>
#include <cuda_fp16.h>
#include <cstdint>
#include <cstddef>

// Problem constants
#define B_  4
#define S_  1024
#define E_  1024
#define H_  16
#define HD_ 64
#define ML_ 2048
#define MR  4096   // B*S

typedef __half hf;

// ---------------- static scratch ----------------
__device__ hf    g_wq[3*E_*E_];
__device__ hf    g_wo[E_*E_];
__device__ hf    g_w1[4*E_*E_];
__device__ hf    g_w2[4*E_*E_];
__device__ hf    g_xn[MR*E_];
__device__ hf    g_qkvh[(size_t)MR*3*E_];
__device__ hf    g_ao[MR*E_];
__device__ float g_x1 [MR*E_];
__device__ hf    g_xm[MR*E_];
__device__ hf    g_h1[(size_t)MR*4*E_];

// ---------------- helpers ----------------
__device__ __forceinline__ uint32_t smem_u32(const void* p) {
    uint32_t a;
    asm("{ .reg .u64 t; cvta.to.shared.u64 t, %1; cvt.u32.u64 %0, t; }" : "=r"(a) : "l"(p));
    return a;
}
__device__ __forceinline__ void ldsm_x4(uint32_t* r, uint32_t addr) {
    asm volatile("ldmatrix.sync.aligned.m8n8.x4.shared.b16 {%0,%1,%2,%3}, [%4];"
        : "=r"(r[0]), "=r"(r[1]), "=r"(r[2]), "=r"(r[3]) : "r"(addr));
}
__device__ __forceinline__ void ldsm_x4_t(uint32_t* r, uint32_t addr) {
    asm volatile("ldmatrix.sync.aligned.m8n8.x4.trans.shared.b16 {%0,%1,%2,%3}, [%4];"
        : "=r"(r[0]), "=r"(r[1]), "=r"(r[2]), "=r"(r[3]) : "r"(addr));
}
__device__ __forceinline__ void mma_f16(float* d, const uint32_t* a, uint32_t b0, uint32_t b1) {
    asm volatile("mma.sync.aligned.m16n8k16.row.col.f32.f16.f16.f32 "
        "{%0,%1,%2,%3},{%4,%5,%6,%7},{%8,%9},{%0,%1,%2,%3};"
        : "+f"(d[0]), "+f"(d[1]), "+f"(d[2]), "+f"(d[3])
        : "r"(a[0]), "r"(a[1]), "r"(a[2]), "r"(a[3]), "r"(b0), "r"(b1));
}
__device__ __forceinline__ uint32_t pack2h(hf a, hf b) {
    union { hf h[2]; uint32_t u; } t;
    t.h[0] = a; t.h[1] = b;
    return t.u;
}
__device__ __forceinline__ void cp16(uint32_t s, const void* g) {
    asm volatile("cp.async.cg.shared.global [%0], [%1], 16;" :: "r"(s), "l"(g));
}
#define CP_COMMIT() asm volatile("cp.async.commit_group;" ::: "memory")
#define CP_WAIT2()  asm volatile("cp.async.wait_group 2;" ::: "memory")
#define CP_WAIT0()  asm volatile("cp.async.wait_group 0;" ::: "memory")

// ---------------- merged weight conversion (fp32 -> fp16) ----------------
#define NQ4 (3*E_*E_/4)
#define NO4 (E_*E_/4)
#define NW4 (4*E_*E_/4)
__global__ __launch_bounds__(256) void cvt_all(const float* __restrict__ iq,
                                               const float* __restrict__ io,
                                               const float* __restrict__ i1,
                                               const float* __restrict__ i2,
                                               hf* __restrict__ oq, hf* __restrict__ oo,
                                               hf* __restrict__ o1, hf* __restrict__ o2)
{
    int i = blockIdx.x * blockDim.x + threadIdx.x;
    const float* in;
    hf* out;
    if (i < NQ4) { in = iq; out = oq; }
    else if (i < NQ4 + NO4) { i -= NQ4; in = io; out = oo; }
    else if (i < NQ4 + NO4 + NW4) { i -= NQ4 + NO4; in = i1; out = o1; }
    else { i -= NQ4 + NO4 + NW4; in = i2; out = o2; }
    float4 v = ((const float4*)in)[i];
    union { hf h[4]; uint2 u; } p;
    p.h[0] = __float2half_rn(v.x);
    p.h[1] = __float2half_rn(v.y);
    p.h[2] = __float2half_rn(v.z);
    p.h[3] = __float2half_rn(v.w);
    ((uint2*)out)[i] = p.u;
}

// ---------------- LayerNorm -> fp16 ----------------
__global__ __launch_bounds__(256) void ln_h(const float* __restrict__ x,
                                            const float* __restrict__ gamma,
                                            const float* __restrict__ beta,
                                            hf* __restrict__ y)
{
    const int row = blockIdx.x;
    const int t = threadIdx.x;
    const float* xr = x + (size_t)row * E_;
    float4 xv = *(const float4*)(xr + t * 4);
    float s = xv.x + xv.y + xv.z + xv.w;
    float sq = xv.x*xv.x + xv.y*xv.y + xv.z*xv.z + xv.w*xv.w;
    #pragma unroll
    for (int o = 16; o > 0; o >>= 1) {
        s  += __shfl_down_sync(0xffffffffu, s, o);
        sq += __shfl_down_sync(0xffffffffu, sq, o);
    }
    __shared__ float sa[8], sb[8];
    const int w = t >> 5, lane = t & 31;
    if (lane == 0) { sa[w] = s; sb[w] = sq; }
    __syncthreads();
    float ts = 0.f, tq = 0.f;
    #pragma unroll
    for (int k = 0; k < 8; k++) { ts += sa[k]; tq += sb[k]; }
    const float mean = ts * (1.0f / E_);
    const float var = tq * (1.0f / E_) - mean * mean;
    const float rstd = rsqrtf(var + 1e-5f);
    float4 gv = *(const float4*)(gamma + t * 4);
    float4 bv = *(const float4*)(beta + t * 4);
    union { hf b[4]; uint2 u; } p;
    p.b[0] = __float2half_rn((xv.x - mean) * rstd * gv.x + bv.x);
    p.b[1] = __float2half_rn((xv.y - mean) * rstd * gv.y + bv.y);
    p.b[2] = __float2half_rn((xv.z - mean) * rstd * gv.z + bv.z);
    p.b[3] = __float2half_rn((xv.w - mean) * rstd * gv.w + bv.w);
    *(uint2*)(y + (size_t)row * E_ + t * 4) = p.u;
}

// ---------------- single-term fp16 GEMM, cp.async 4-stage ----------------
#define GK 32
#define RS 40
#define MAT_SZ (128 * RS * 2)       // 10240 B
#define STAGE_SZ (2 * MAT_SZ)       // 20480 B
#define NSTG 4
#define BIAS_OFF (NSTG * STAGE_SZ)  // 81920
#define GSMEM (BIAS_OFF + 512)

// OUT: 0 = fp32 C; 2 = fp16; 3 = fp16 with 0.125 scale on cols < E_ (QKV: fold q scale)
template <int RELU, int RES, int OUT>
__global__ __launch_bounds__(256, 1)
void gemm_1t(const hf* __restrict__ A, const hf* __restrict__ Bm,
             const float* __restrict__ bias, const float* __restrict__ res,
             float* __restrict__ C, hf* __restrict__ Chi,
             int M, int N, int K)
{
    extern __shared__ char smem[];
    const int tid = threadIdx.x;
    const int lane = tid & 31;
    const int wid = tid >> 5;
    const int wm = wid & 1;
    const int wn = wid >> 1;
    const int bm = blockIdx.y * 128;
    const int bn = blockIdx.x * 128;

    float acc[4][4][4];
    #pragma unroll
    for (int a = 0; a < 4; a++)
        #pragma unroll
        for (int b = 0; b < 4; b++)
            #pragma unroll
            for (int c = 0; c < 4; c++) acc[a][b][c] = 0.f;

    const int prow = tid >> 2;
    const int pc = tid & 3;
    const uint32_t sb0 = smem_u32(smem);
    const int arow = wm * 64 + (lane & 15);
    const int brow = wn * 32 + (lane & 15);
    const int acol = (lane >> 4) * 8;

    if (tid < 128) *(float*)(smem + BIAS_OFF + tid * 4) = bias[bn + tid];

    const int NK = K / GK;

    auto issue_stage = [&](int stage, int ko) {
        const uint32_t sb = sb0 + stage * STAGE_SZ;
        #pragma unroll
        for (int rep = 0; rep < 2; rep++) {
            const int row = prow + rep * 64;
            const uint32_t so = (uint32_t)row * (RS * 2) + pc * 16;
            const size_t ga = (size_t)(bm + row) * K + ko + pc * 8;
            const size_t gb = (size_t)(bn + row) * K + ko + pc * 8;
            cp16(sb + so, A + ga);
            cp16(sb + MAT_SZ + so, Bm + gb);
        }
    };

    #pragma unroll
    for (int st = 0; st < NSTG - 1; st++) {
        issue_stage(st, st * GK);
        CP_COMMIT();
    }

    for (int kt = 0; kt < NK; kt++) {
        const int buf = kt & 3;
        CP_WAIT2();
        __syncthreads();

        const uint32_t base = sb0 + buf * STAGE_SZ;
        #pragma unroll
        for (int k0 = 0; k0 < 2; k0++) {
            uint32_t ah[4][4];
            #pragma unroll
            for (int mi = 0; mi < 4; mi++) {
                const uint32_t ad = base + (uint32_t)(arow + mi * 16) * (RS * 2) + (k0 * 16 + acol) * 2;
                ldsm_x4(ah[mi], ad);
            }
            uint32_t bq[2][4];
            #pragma unroll
            for (int nb = 0; nb < 2; nb++) {
                const uint32_t bd = base + MAT_SZ + (uint32_t)(brow + nb * 16) * (RS * 2) + (k0 * 16 + acol) * 2;
                ldsm_x4(bq[nb], bd);
            }
            #pragma unroll
            for (int mi = 0; mi < 4; mi++) {
                #pragma unroll
                for (int nb = 0; nb < 2; nb++) {
                    mma_f16(acc[mi][nb*2],   ah[mi], bq[nb][0], bq[nb][2]);
                    mma_f16(acc[mi][nb*2+1], ah[mi], bq[nb][1], bq[nb][3]);
                }
            }
        }

        if (kt + NSTG - 1 < NK) issue_stage((kt + NSTG - 1) & 3, (kt + NSTG - 1) * GK);
        CP_COMMIT();
    }

    // ---------------- epilogue ----------------
    float bv[4][2];
    #pragma unroll
    for (int ni = 0; ni < 4; ni++) {
        const int c0 = wn * 32 + ni * 8 + (lane & 3) * 2;
        bv[ni][0] = *(const float*)(smem + BIAS_OFF + c0 * 4);
        bv[ni][1] = *(const float*)(smem + BIAS_OFF + (c0 + 1) * 4);
    }
    #pragma unroll
    for (int mi = 0; mi < 4; mi++) {
        const int r0 = bm + wm * 64 + mi * 16 + (lane >> 2);
        #pragma unroll
        for (int ni = 0; ni < 4; ni++) {
            const int c0 = bn + wn * 32 + ni * 8 + (lane & 3) * 2;
            #pragma unroll
            for (int h = 0; h < 2; h++) {
                const int r = r0 + h * 8;
                float v0 = acc[mi][ni][h*2]   + bv[ni][0];
                float v1 = acc[mi][ni][h*2+1] + bv[ni][1];
                if (RELU) { v0 = fmaxf(v0, 0.f); v1 = fmaxf(v1, 0.f); }
                const size_t off = (size_t)r * N + c0;
                if (RES) {
                    float2 rr = *(const float2*)(res + off);
                    v0 += rr.x; v1 += rr.y;
                }
                if (OUT == 2) {
                    *(uint32_t*)(Chi + off) = pack2h(__float2half_rn(v0), __float2half_rn(v1));
                } else if (OUT == 3) {
                    const float sc = (c0 < E_) ? 0.125f : 1.0f;
                    *(uint32_t*)(Chi + off) = pack2h(__float2half_rn(v0 * sc), __float2half_rn(v1 * sc));
                } else {
                    *(float2*)(C + off) = make_float2(v0, v1);
                }
            }
        }
    }
}

// ---------------- fp16 flash attention: 1-term QK/PV, cp.async double-buffered K/V ----------------
#define ARS 72
#define ATILE (64 * ARS * 2)       // 9216 B
#define A_QH 0
#define A_K0 (ATILE)               // K stages at ATILE, 2*ATILE
#define A_V0 (3*ATILE)             // V stages at 3*ATILE, 4*ATILE
#define A_RP (5*ATILE)             // 46080: rel_pos row cache (1088 floats)
#define ASMEM (5*ATILE + 1088*4)

__global__ __launch_bounds__(128)
void attn_mma(const hf* __restrict__ qkvh,
              const float* __restrict__ rel_pos,
              hf* __restrict__ outp)
{
    extern __shared__ char smem[];
    const uint32_t sb = smem_u32(smem);
    const int tid = threadIdx.x;
    const int lane = tid & 31;
    const int w = tid >> 5;
    const int qt = gridDim.x - 1 - blockIdx.x;   // heavy tiles first
    const int q0 = qt * 64;
    const int h = blockIdx.y;
    const int b = blockIdx.z;

    const int rl = lane >> 2;
    const int cl = (lane & 3) * 2;

    // load Q tile (already scaled by 0.125 in QKV epilogue)
    #pragma unroll
    for (int p = 0; p < 4; p++) {
        const int chunk = tid + p * 128;
        const int row = chunk >> 3;
        const int c16 = chunk & 7;
        const size_t g = (size_t)(b * S_ + q0 + row) * (3 * E_) + h * 64 + c16 * 8;
        *(uint4*)(smem + A_QH + row * (ARS * 2) + c16 * 16) = *(const uint4*)(qkvh + g);
    }
    // cache rel_pos[h][0 .. q0+63] in smem
    {
        const float* rp = rel_pos + (size_t)h * ML_;
        for (int i = tid; i < q0 + 64; i += 128)
            ((float*)(smem + A_RP))[i] = rp[i];
    }

    auto issue_kv = [&](int st, int kt) {
        const uint32_t kbase = sb + A_K0 + st * ATILE;
        const uint32_t vbase = sb + A_V0 + st * ATILE;
        #pragma unroll
        for (int p = 0; p < 4; p++) {
            const int chunk = tid + p * 128;
            const int row = chunk >> 3;
            const int c16 = chunk & 7;
            const size_t gk = (size_t)(b * S_ + kt * 64 + row) * (3 * E_) + E_ + h * 64 + c16 * 8;
            const uint32_t so = (uint32_t)row * (ARS * 2) + c16 * 16;
            cp16(kbase + so, qkvh + gk);
            cp16(vbase + so, qkvh + gk + E_);
        }
    };

    issue_kv(0, 0);
    CP_COMMIT();

    float o[8][4];
    #pragma unroll
    for (int t = 0; t < 8; t++)
        #pragma unroll
        for (int e = 0; e < 4; e++) o[t][e] = 0.f;
    float m0 = -1e30f, m1 = -1e30f, l0 = 0.f, l1 = 0.f;

    const int nk = qt + 1;
    const float* rpc = (const float*)(smem + A_RP);

    for (int kt = 0; kt < nk; kt++) {
        const int buf = kt & 1;
        CP_WAIT0();
        __syncthreads();
        if (kt + 1 < nk) { issue_kv(buf ^ 1, kt + 1); CP_COMMIT(); }

        const uint32_t kst = sb + A_K0 + buf * ATILE;
        const uint32_t vst = sb + A_V0 + buf * ATILE;

        float s[8][4];
        #pragma unroll
        for (int t = 0; t < 8; t++)
            #pragma unroll
            for (int e = 0; e < 4; e++) s[t][e] = 0.f;

        #pragma unroll
        for (int d4 = 0; d4 < 4; d4++) {
            uint32_t qh_[4];
            const uint32_t qa = sb + A_QH + (uint32_t)(w * 16 + (lane & 15)) * (ARS * 2) + (d4 * 16 + (lane >> 4) * 8) * 2;
            ldsm_x4(qh_, qa);
            #pragma unroll
            for (int nb = 0; nb < 4; nb++) {
                uint32_t kh_[4];
                const uint32_t ka = kst + (uint32_t)(nb * 16 + (lane & 15)) * (ARS * 2) + (d4 * 16 + (lane >> 4) * 8) * 2;
                ldsm_x4(kh_, ka);
                mma_f16(s[nb*2],   qh_, kh_[0], kh_[2]);
                mma_f16(s[nb*2+1], qh_, kh_[1], kh_[3]);
            }
        }

        const bool diag = (kt == qt);
        const int i0 = w * 16 + rl;
        const int i1 = i0 + 8;
        const int base = q0 - kt * 64;     // global (i - j) = base + irow_local - c_local
        float tmax0 = -1e30f, tmax1 = -1e30f;
        #pragma unroll
        for (int t = 0; t < 8; t++) {
            const int c0 = t * 8 + cl;
            #pragma unroll
            for (int e = 0; e < 4; e++) {
                const int irow = (e < 2) ? i0 : i1;
                const int c = c0 + (e & 1);
                float val = s[t][e] + rpc[base + irow - c];
                if (diag && c > irow) val = -1e30f;
                s[t][e] = val;
                if (e < 2) tmax0 = fmaxf(tmax0, val);
                else       tmax1 = fmaxf(tmax1, val);
            }
        }
        #pragma unroll
        for (int xo = 1; xo <= 2; xo <<= 1) {
            tmax0 = fmaxf(tmax0, __shfl_xor_sync(0xffffffffu, tmax0, xo));
            tmax1 = fmaxf(tmax1, __shfl_xor_sync(0xffffffffu, tmax1, xo));
        }
        const float mn0 = fmaxf(m0, tmax0);
        const float mn1 = fmaxf(m1, tmax1);
        const float corr0 = __expf(m0 - mn0);
        const float corr1 = __expf(m1 - mn1);
        m0 = mn0; m1 = mn1;

        float rs0 = 0.f, rs1 = 0.f;
        #pragma unroll
        for (int t = 0; t < 8; t++) {
            s[t][0] = __expf(s[t][0] - mn0);
            s[t][1] = __expf(s[t][1] - mn0);
            s[t][2] = __expf(s[t][2] - mn1);
            s[t][3] = __expf(s[t][3] - mn1);
            rs0 += s[t][0] + s[t][1];
            rs1 += s[t][2] + s[t][3];
        }
        #pragma unroll
        for (int xo = 1; xo <= 2; xo <<= 1) {
            rs0 += __shfl_xor_sync(0xffffffffu, rs0, xo);
            rs1 += __shfl_xor_sync(0xffffffffu, rs1, xo);
        }
        l0 = l0 * corr0 + rs0;
        l1 = l1 * corr1 + rs1;
        #pragma unroll
        for (int t = 0; t < 8; t++) {
            o[t][0] *= corr0; o[t][1] *= corr0;
            o[t][2] *= corr1; o[t][3] *= corr1;
        }

        #pragma unroll
        for (int kb = 0; kb < 4; kb++) {
            uint32_t pa[4];
            {
                const float* sA = s[2*kb];
                const float* sB = s[2*kb+1];
                pa[0] = pack2h(__float2half_rn(sA[0]), __float2half_rn(sA[1]));
                pa[1] = pack2h(__float2half_rn(sA[2]), __float2half_rn(sA[3]));
                pa[2] = pack2h(__float2half_rn(sB[0]), __float2half_rn(sB[1]));
                pa[3] = pack2h(__float2half_rn(sB[2]), __float2half_rn(sB[3]));
            }
            #pragma unroll
            for (int nb = 0; nb < 4; nb++) {
                uint32_t vh_[4];
                const uint32_t va = vst + (uint32_t)(kb * 16 + (lane & 15)) * (ARS * 2) + (nb * 16 + (lane >> 4) * 8) * 2;
                ldsm_x4_t(vh_, va);
                mma_f16(o[nb*2],   pa, vh_[0], vh_[1]);
                mma_f16(o[nb*2+1], pa, vh_[2], vh_[3]);
            }
        }
    }

    const float inv0 = 1.0f / l0;
    const float inv1 = 1.0f / l1;
    const int tok0 = b * S_ + q0 + w * 16 + rl;
    const int tok1 = tok0 + 8;
    #pragma unroll
    for (int t = 0; t < 8; t++) {
        const int col = h * 64 + t * 8 + cl;
        const size_t o0 = (size_t)tok0 * E_ + col;
        const size_t o1 = (size_t)tok1 * E_ + col;
        *(uint32_t*)(outp + o0) = pack2h(__float2half_rn(o[t][0] * inv0), __float2half_rn(o[t][1] * inv0));
        *(uint32_t*)(outp + o1) = pack2h(__float2half_rn(o[t][2] * inv1), __float2half_rn(o[t][3] * inv1));
    }
}

// ---------------- launch ----------------
extern "C" void kernel_launch(void* const* d_in, const int* in_sizes, int n_in,
                              void* d_out, int out_size)
{
    const float* x         = (const float*)d_in[0];
    const float* rel_pos   = (const float*)d_in[1];
    const float* in_proj_w = (const float*)d_in[2];
    const float* in_proj_b = (const float*)d_in[3];
    const float* out_w     = (const float*)d_in[4];
    const float* out_b     = (const float*)d_in[5];
    const float* w1        = (const float*)d_in[6];
    const float* b1        = (const float*)d_in[7];
    const float* w2        = (const float*)d_in[8];
    const float* b2        = (const float*)d_in[9];
    const float* ln1_g     = (const float*)d_in[10];
    const float* ln1_b     = (const float*)d_in[11];
    const float* ln2_g     = (const float*)d_in[12];
    const float* ln2_b     = (const float*)d_in[13];
    float* out = (float*)d_out;

    hf *wq, *wo, *w1p, *w2p, *xn, *ao, *xm, *h1, *qkvh;
    float *x1;
    cudaGetSymbolAddress((void**)&wq, g_wq);  cudaGetSymbolAddress((void**)&wo, g_wo);
    cudaGetSymbolAddress((void**)&w1p, g_w1); cudaGetSymbolAddress((void**)&w2p, g_w2);
    cudaGetSymbolAddress((void**)&xn, g_xn);  cudaGetSymbolAddress((void**)&ao, g_ao);
    cudaGetSymbolAddress((void**)&xm, g_xm);  cudaGetSymbolAddress((void**)&h1, g_h1);
    cudaGetSymbolAddress((void**)&qkvh, g_qkvh);
    cudaGetSymbolAddress((void**)&x1, g_x1);

    cudaFuncSetAttribute(gemm_1t<0,0,3>, cudaFuncAttributeMaxDynamicSharedMemorySize, GSMEM);
    cudaFuncSetAttribute(gemm_1t<0,1,0>, cudaFuncAttributeMaxDynamicSharedMemorySize, GSMEM);
    cudaFuncSetAttribute(gemm_1t<1,0,2>, cudaFuncAttributeMaxDynamicSharedMemorySize, GSMEM);
    cudaFuncSetAttribute(attn_mma, cudaFuncAttributeMaxDynamicSharedMemorySize, ASMEM);

    // 0) all weight conversions in one launch
    cvt_all<<<(NQ4 + NO4 + 2*NW4 + 255)/256, 256>>>(in_proj_w, out_w, w1, w2, wq, wo, w1p, w2p);

    // 1) LN1 -> xn (fp16)
    ln_h<<<MR, 256>>>(x, ln1_g, ln1_b, xn);
    // 2) QKV -> fp16 (Q cols pre-scaled by 0.125)
    gemm_1t<0,0,3><<<dim3(3*E_/128, MR/128), 256, GSMEM>>>(
        xn, wq, in_proj_b, nullptr, nullptr, qkvh, MR, 3*E_, E_);
    // 3) attention -> ao (fp16)
    attn_mma<<<dim3(S_/64, H_, B_), 128, ASMEM>>>(qkvh, rel_pos, ao);
    // 4) out-proj + residual -> x1 fp32
    gemm_1t<0,1,0><<<dim3(E_/128, MR/128), 256, GSMEM>>>(
        ao, wo, out_b, x, x1, nullptr, MR, E_, E_);
    // 5) LN2 -> xm (fp16)
    ln_h<<<MR, 256>>>(x1, ln2_g, ln2_b, xm);
    // 6) MLP up + ReLU -> h1 (fp16)
    gemm_1t<1,0,2><<<dim3(4*E_/128, MR/128), 256, GSMEM>>>(
        xm, w1p, b1, nullptr, nullptr, h1, MR, 4*E_, E_);
    // 7) MLP down + residual -> out fp32
    gemm_1t<0,1,0><<<dim3(E_/128, MR/128), 256, GSMEM>>>(
        h1, w2p, b2, x1, out, nullptr, MR, E_, 4*E_);
}